// round 9
// baseline (speedup 1.0000x reference)
#include <cuda_runtime.h>
#include <cuda_fp16.h>
#include <cstdint>

// Problem constants
#define Bb   2
#define Ss   2048
#define Hh   2048
#define NHh  16
#define HDd  128
#define Mm   4096   // B*S

// ---------------------------------------------------------------------------
// Scratch (device globals; no allocation allowed)
// ---------------------------------------------------------------------------
__device__ __half g_Xh[(size_t)Mm * Hh];
__device__ __half g_Xl[(size_t)Mm * Hh];
__device__ __half g_Qh[(size_t)Mm * Hh];
__device__ __half g_Ql[(size_t)Mm * Hh];
__device__ __half g_Ks[(size_t)Mm * Hh];
__device__ __half g_Vs[(size_t)Mm * Hh];
__device__ __half g_AOh[(size_t)Mm * Hh];
__device__ __half g_Wt[4][(size_t)Hh * Hh];

// ---------------------------------------------------------------------------
// PTX helpers (sm_80-level only: legal in compute_103 PTX)
// ---------------------------------------------------------------------------
__device__ __forceinline__ uint32_t smem_to_u32(const void* p) {
    uint32_t a;
    asm("{ .reg .u64 t; cvta.to.shared.u64 t, %1; cvt.u32.u64 %0, t; }"
        : "=r"(a) : "l"(p));
    return a;
}
__device__ __forceinline__ void cp16(uint32_t s, const void* g) {
    asm volatile("cp.async.cg.shared.global [%0], [%1], 16;" :: "r"(s), "l"(g));
}
#define CP_COMMIT() asm volatile("cp.async.commit_group;" ::: "memory")
#define CP_WAIT0()  asm volatile("cp.async.wait_group 0;" ::: "memory")
#define CP_WAIT1()  asm volatile("cp.async.wait_group 1;" ::: "memory")

__device__ __forceinline__ void ldm_x4(uint32_t& r0, uint32_t& r1, uint32_t& r2,
                                       uint32_t& r3, uint32_t addr) {
    asm volatile("ldmatrix.sync.aligned.m8n8.x4.shared.b16 {%0,%1,%2,%3}, [%4];"
                 : "=r"(r0), "=r"(r1), "=r"(r2), "=r"(r3) : "r"(addr));
}
__device__ __forceinline__ void ldm_x4t(uint32_t& r0, uint32_t& r1, uint32_t& r2,
                                        uint32_t& r3, uint32_t addr) {
    asm volatile("ldmatrix.sync.aligned.m8n8.x4.trans.shared.b16 {%0,%1,%2,%3}, [%4];"
                 : "=r"(r0), "=r"(r1), "=r"(r2), "=r"(r3) : "r"(addr));
}
__device__ __forceinline__ void ldm_x2(uint32_t& r0, uint32_t& r1, uint32_t addr) {
    asm volatile("ldmatrix.sync.aligned.m8n8.x2.shared.b16 {%0,%1}, [%2];"
                 : "=r"(r0), "=r"(r1) : "r"(addr));
}
__device__ __forceinline__ void mma_f16(float* c, const uint32_t* a, const uint32_t* b) {
    asm volatile("mma.sync.aligned.m16n8k16.row.col.f32.f16.f16.f32 "
                 "{%0,%1,%2,%3}, {%4,%5,%6,%7}, {%8,%9}, {%0,%1,%2,%3};"
                 : "+f"(c[0]), "+f"(c[1]), "+f"(c[2]), "+f"(c[3])
                 : "r"(a[0]), "r"(a[1]), "r"(a[2]), "r"(a[3]), "r"(b[0]), "r"(b[1]));
}

// Fast exp2 on the FMA pipe (deg-5 poly, f in [-0.5,0.5]); rel err ~2.4e-6.
__device__ __forceinline__ float exp2p(float t) {
    t = fmaxf(t, -120.f);
    float fn = t + 12582912.f;
    int   n  = __float_as_int(fn) - 0x4B400000;
    float f  = t - (fn - 12582912.f);
    float p  = 1.3333558146428443e-3f;
    p = fmaf(p, f, 9.6181291076284772e-3f);
    p = fmaf(p, f, 5.5504108664821580e-2f);
    p = fmaf(p, f, 2.4022650695910071e-1f);
    p = fmaf(p, f, 6.9314718055994531e-1f);
    p = fmaf(p, f, 1.0f);
    return p * __int_as_float((n + 127) << 23);
}

__device__ __forceinline__ uint32_t packh(float x, float y) {
    __half2 t = __floats2half2_rn(x, y);
    return *reinterpret_cast<uint32_t*>(&t);
}

// ---------------------------------------------------------------------------
// Conversions
// ---------------------------------------------------------------------------
__global__ void convert_split(const float2* __restrict__ X,
                              __half2* __restrict__ Xh,
                              __half2* __restrict__ Xl, int n2)
{
    int i = blockIdx.x * blockDim.x + threadIdx.x;
    if (i >= n2) return;
    float2 v = X[i];
    __half h0 = __float2half_rn(v.x);
    __half h1 = __float2half_rn(v.y);
    float r0 = v.x - __half2float(h0);
    float r1 = v.y - __half2float(h1);
    Xh[i] = __half2(h0, h1);
    Xl[i] = __half2(__float2half_rn(r0), __float2half_rn(r1));
}

// Fused transpose + convert for all 4 weights (z selects the matrix)
__global__ void transpose_convert4(const float* __restrict__ w0,
                                   const float* __restrict__ w1,
                                   const float* __restrict__ w2,
                                   const float* __restrict__ w3,
                                   __half* __restrict__ T)
{
    __shared__ float t[32][33];
    const float* W = (blockIdx.z == 0) ? w0 : (blockIdx.z == 1) ? w1
                   : (blockIdx.z == 2) ? w2 : w3;
    __half* Td = T + (size_t)blockIdx.z * Hh * Hh;
    const int n0 = blockIdx.x * 32, k0 = blockIdx.y * 32;
    const int tx = threadIdx.x, ty = threadIdx.y;   // (32, 8)
#pragma unroll
    for (int i = 0; i < 4; i++)
        t[ty + 8 * i][tx] = W[(size_t)(k0 + ty + 8 * i) * Hh + n0 + tx];
    __syncthreads();
#pragma unroll
    for (int i = 0; i < 4; i++)
        Td[(size_t)(n0 + ty + 8 * i) * Hh + k0 + tx] =
            __float2half_rn(t[tx][ty + 8 * i]);
}

// ---------------------------------------------------------------------------
// GEMM common geometry: BK=64, 2-stage double buffer, 2 CTAs/SM.
// ---------------------------------------------------------------------------
#define BKg   64
#define PADR  72                             // 64 halfs + 8 pad (144B rows)
#define TILE_HALFS (128 * PADR)              // 9216
#define TILE_B ((uint32_t)(TILE_HALFS * 2))  // 18432 bytes
#define QKV_STAGE_B (3u * TILE_B)            // Ah, Al, B = 55296
#define QKV_SMEM (2 * 3 * (int)TILE_B)       // 110592
#define PROJ_STAGE_B (2u * TILE_B)           // 36864
#define PROJ_SMEM (2 * 2 * (int)TILE_B)      // 73728

// Load one 128x64 half tile, 16B chunks: r = tid>>1, chunk col (tid&1)*4 + cc
__device__ __forceinline__ void stage_load_rt(uint32_t sb, bool asplit,
    const __half* __restrict__ Ah, const __half* __restrict__ Al,
    const __half* __restrict__ Bs, uint32_t b_off, int bm, int bn, int k0, int tid)
{
    const int r = tid >> 1;
    const int c = (tid & 1) * 4;
#pragma unroll
    for (int cc = 0; cc < 4; cc++) {
        const uint32_t so = (uint32_t)(r * PADR + (c + cc) * 8) * 2;
        const size_t go = (size_t)k0 + (c + cc) * 8;
        cp16(sb + so, Ah + (size_t)(bm + r) * Hh + go);
        if (asplit)
            cp16(sb + TILE_B + so, Al + (size_t)(bm + r) * Hh + go);
        cp16(sb + b_off + so, Bs + (size_t)(bn + r) * Hh + go);
    }
}

// ---------------------------------------------------------------------------
// Merged QKV GEMM: z = 0 (Q: A split, hi/lo out), 1 (K: single, single out),
// 2 (V: single, single out). CTA 128x128, BK=64, 2-stage, 2 CTAs/SM.
// ---------------------------------------------------------------------------
__global__ __launch_bounds__(256, 2)
void qkv_mma(const __half* __restrict__ Xh, const __half* __restrict__ Xl,
             const __half* __restrict__ Wt,
             const float* __restrict__ bq, const float* __restrict__ bk,
             const float* __restrict__ bv,
             __half* __restrict__ Qh, __half* __restrict__ Ql,
             __half* __restrict__ Ks, __half* __restrict__ Vs)
{
    extern __shared__ __half smem[];
    const uint32_t sbase = smem_to_u32(smem);
    const int tid = threadIdx.x;
    const int wid = tid >> 5, lane = tid & 31;
    const int z = blockIdx.z;
    const bool asplit = (z == 0);
    const __half* Bs = Wt + (size_t)z * Hh * Hh;
    const float* bias = (z == 0) ? bq : (z == 1) ? bk : bv;
    const int bn = blockIdx.x * 128, bm = blockIdx.y * 128;
    const int wm = (wid >> 2) * 64;
    const int wn = (wid & 3) * 32;

    float acc[4][4][4];
#pragma unroll
    for (int i = 0; i < 4; i++)
#pragma unroll
        for (int j = 0; j < 4; j++)
#pragma unroll
            for (int q = 0; q < 4; q++) acc[i][j][q] = 0.f;

    const int NIT = Hh / BKg;   // 32
    stage_load_rt(sbase, asplit, Xh, Xl, Bs, 2 * TILE_B, bm, bn, 0, tid);
    CP_COMMIT();
    stage_load_rt(sbase + QKV_STAGE_B, asplit, Xh, Xl, Bs, 2 * TILE_B,
                  bm, bn, BKg, tid);
    CP_COMMIT();

    const int arow = lane & 15;
    const int acol8 = (lane >> 4) << 3;
    const int brow = lane & 7;
    const int bcol8 = ((lane >> 3) & 1) << 3;

    for (int kt = 0; kt < NIT; kt++) {
        if (kt + 1 < NIT) { CP_WAIT1(); } else { CP_WAIT0(); }
        __syncthreads();
        const uint32_t sb = sbase + (uint32_t)(kt & 1) * QKV_STAGE_B;

#pragma unroll
        for (int ks = 0; ks < 4; ks++) {
            const int k0 = ks * 16;
            uint32_t bF[4][2];
#pragma unroll
            for (int ni = 0; ni < 4; ni++) {
                const uint32_t off =
                    (uint32_t)((wn + ni * 8 + brow) * PADR + k0 + bcol8) * 2;
                ldm_x2(bF[ni][0], bF[ni][1], sb + 2 * TILE_B + off);
            }
#pragma unroll
            for (int mi = 0; mi < 4; mi++) {
                const uint32_t off =
                    (uint32_t)((wm + mi * 16 + arow) * PADR + k0 + acol8) * 2;
                uint32_t aH[4];
                ldm_x4(aH[0], aH[1], aH[2], aH[3], sb + off);
#pragma unroll
                for (int ni = 0; ni < 4; ni++)
                    mma_f16(acc[mi][ni], aH, bF[ni]);
                if (asplit) {
                    uint32_t aL[4];
                    ldm_x4(aL[0], aL[1], aL[2], aL[3], sb + TILE_B + off);
#pragma unroll
                    for (int ni = 0; ni < 4; ni++)
                        mma_f16(acc[mi][ni], aL, bF[ni]);
                }
            }
        }

        __syncthreads();
        if (kt + 2 < NIT) {
            stage_load_rt(sb, asplit, Xh, Xl, Bs, 2 * TILE_B,
                          bm, bn, (kt + 2) * BKg, tid);
            CP_COMMIT();
        }
    }

    const int fr = lane >> 2;
    const int fc = (lane & 3) * 2;
#pragma unroll
    for (int mi = 0; mi < 4; mi++) {
#pragma unroll
        for (int ni = 0; ni < 4; ni++) {
            const int n0 = bn + wn + ni * 8 + fc;
            const float b0 = bias[n0], b1 = bias[n0 + 1];
#pragma unroll
            for (int half = 0; half < 2; half++) {
                const int m = bm + wm + mi * 16 + fr + half * 8;
                float v0 = acc[mi][ni][half * 2 + 0] + b0;
                float v1 = acc[mi][ni][half * 2 + 1] + b1;
                const int bb = m >> 11;
                const int ss = m & (Ss - 1);
                const int hh = n0 >> 7;
                const int dd = n0 & (HDd - 1);
                const size_t idx =
                    (((size_t)(bb * NHh + hh) * Ss) + ss) * HDd + dd;
                if (z == 0) {
                    __half h0 = __float2half_rn(v0);
                    __half h1 = __float2half_rn(v1);
                    float r0 = v0 - __half2float(h0);
                    float r1 = v1 - __half2float(h1);
                    *(__half2*)&Qh[idx] = __half2(h0, h1);
                    *(__half2*)&Ql[idx] = __half2(
                        __float2half_rn(r0), __float2half_rn(r1));
                } else if (z == 1) {
                    *(__half2*)&Ks[idx] = __floats2half2_rn(v0, v1);
                } else {
                    *(__half2*)&Vs[idx] = __floats2half2_rn(v0, v1);
                }
            }
        }
    }
}

// ---------------------------------------------------------------------------
// Output projection GEMM: C[M,N] = A @ B^T + bias, fp32 out, single-A.
// ---------------------------------------------------------------------------
__global__ __launch_bounds__(256, 2)
void proj_mma(const __half* __restrict__ Ah, const __half* __restrict__ Bw,
              const float* __restrict__ bias, float* __restrict__ Cf)
{
    extern __shared__ __half smem[];
    const uint32_t sbase = smem_to_u32(smem);
    const int tid = threadIdx.x;
    const int wid = tid >> 5, lane = tid & 31;
    const int bn = blockIdx.x * 128, bm = blockIdx.y * 128;
    const int wm = (wid >> 2) * 64;
    const int wn = (wid & 3) * 32;

    float acc[4][4][4];
#pragma unroll
    for (int i = 0; i < 4; i++)
#pragma unroll
        for (int j = 0; j < 4; j++)
#pragma unroll
            for (int q = 0; q < 4; q++) acc[i][j][q] = 0.f;

    const int NIT = Hh / BKg;
    stage_load_rt(sbase, false, Ah, nullptr, Bw, TILE_B, bm, bn, 0, tid);
    CP_COMMIT();
    stage_load_rt(sbase + PROJ_STAGE_B, false, Ah, nullptr, Bw, TILE_B,
                  bm, bn, BKg, tid);
    CP_COMMIT();

    const int arow = lane & 15;
    const int acol8 = (lane >> 4) << 3;
    const int brow = lane & 7;
    const int bcol8 = ((lane >> 3) & 1) << 3;

    for (int kt = 0; kt < NIT; kt++) {
        if (kt + 1 < NIT) { CP_WAIT1(); } else { CP_WAIT0(); }
        __syncthreads();
        const uint32_t sb = sbase + (uint32_t)(kt & 1) * PROJ_STAGE_B;

#pragma unroll
        for (int ks = 0; ks < 4; ks++) {
            const int k0 = ks * 16;
            uint32_t bF[4][2];
#pragma unroll
            for (int ni = 0; ni < 4; ni++) {
                const uint32_t off =
                    (uint32_t)((wn + ni * 8 + brow) * PADR + k0 + bcol8) * 2;
                ldm_x2(bF[ni][0], bF[ni][1], sb + TILE_B + off);
            }
#pragma unroll
            for (int mi = 0; mi < 4; mi++) {
                const uint32_t off =
                    (uint32_t)((wm + mi * 16 + arow) * PADR + k0 + acol8) * 2;
                uint32_t aH[4];
                ldm_x4(aH[0], aH[1], aH[2], aH[3], sb + off);
#pragma unroll
                for (int ni = 0; ni < 4; ni++)
                    mma_f16(acc[mi][ni], aH, bF[ni]);
            }
        }

        __syncthreads();
        if (kt + 2 < NIT) {
            stage_load_rt(sb, false, Ah, nullptr, Bw, TILE_B,
                          bm, bn, (kt + 2) * BKg, tid);
            CP_COMMIT();
        }
    }

    const int fr = lane >> 2;
    const int fc = (lane & 3) * 2;
#pragma unroll
    for (int mi = 0; mi < 4; mi++) {
#pragma unroll
        for (int ni = 0; ni < 4; ni++) {
            const int n0 = bn + wn + ni * 8 + fc;
            const float b0 = bias[n0], b1 = bias[n0 + 1];
#pragma unroll
            for (int half = 0; half < 2; half++) {
                const int m = bm + wm + mi * 16 + fr + half * 8;
                float2 w;
                w.x = acc[mi][ni][half * 2 + 0] + b0;
                w.y = acc[mi][ni][half * 2 + 1] + b1;
                *(float2*)&Cf[(size_t)m * Hh + n0] = w;
            }
        }
    }
}

// ---------------------------------------------------------------------------
// HMMA fp16 flash attention: AKT=128, Q_lo resident in smem, single sync/kt.
// CTA: 128 q rows, 8 warps x 16 rows. KV double-buffered cp.async.
// ---------------------------------------------------------------------------
#define AQT 128
#define AKT 128
#define PADV 136
#define Q_TILE_B   (AQT * PADV * 2)        // 34816 bytes (hi), same for lo
#define KV_TILE_B  (AKT * PADV * 2)        // 34816 bytes
#define KV_STAGE_B (2 * KV_TILE_B)         // K, V = 69632 bytes
#define ATT_Q_B    (2 * Q_TILE_B)          // 69632 bytes
#define ATT2_SMEM  (ATT_Q_B + 2 * KV_STAGE_B)   // 208896 bytes

__device__ __forceinline__ void stage_kv2(uint32_t dst, size_t base, int kn0,
    const __half* __restrict__ Ks, const __half* __restrict__ Vs, int tid)
{
#pragma unroll
    for (int i = 0; i < 8; i++) {
        const int idx = i * 256 + tid;
        const int row = idx >> 4, ch = idx & 15;
        const uint32_t so = (uint32_t)(row * PADV + ch * 8) * 2;
        const size_t go = base + (size_t)(kn0 + row) * HDd + ch * 8;
        cp16(dst +             so, Ks + go);
        cp16(dst + KV_TILE_B + so, Vs + go);
    }
}

__global__ __launch_bounds__(256, 1)
void attn_mma(const __half* __restrict__ Qh, const __half* __restrict__ Ql,
              const __half* __restrict__ Ks, const __half* __restrict__ Vs,
              __half* __restrict__ AOh)
{
    extern __shared__ __half asmem[];
    const uint32_t sb = smem_to_u32(asmem);
    const uint32_t QH = sb, QL = sb + Q_TILE_B, KV = sb + ATT_Q_B;
    const int tid = threadIdx.x, wid = tid >> 5, lane = tid & 31;
    const int qi = (int)gridDim.x - 1 - (int)blockIdx.x;   // big tiles first
    const int hh = blockIdx.y, bb = blockIdx.z;
    const size_t base = ((size_t)(bb * NHh + hh)) * Ss * HDd;
    const int q0 = qi * AQT;
    const float Cs = 0.12751745210319466f;   // 128^-0.5 * log2(e)

    const int qrow = wid * 16 + (lane & 15);
    const int qc8 = (lane >> 4) << 3;

    // ---- prologue: Q hi+lo to resident smem; KV tile 0 in flight ----
#pragma unroll
    for (int i = 0; i < 8; i++) {
        const int idx = i * 256 + tid;
        const int row = idx >> 4, ch = idx & 15;
        const uint32_t so = (uint32_t)(row * PADV + ch * 8) * 2;
        const size_t go = base + (size_t)(q0 + row) * HDd + ch * 8;
        cp16(QH + so, Qh + go);
        cp16(QL + so, Ql + go);
    }
    CP_COMMIT();
    stage_kv2(KV, base, 0, Ks, Vs, tid);
    CP_COMMIT();
    CP_WAIT1();          // Q ready
    __syncthreads();

    uint32_t qfh[8][4];
#pragma unroll
    for (int kk = 0; kk < 8; kk++)
        ldm_x4(qfh[kk][0], qfh[kk][1], qfh[kk][2], qfh[kk][3],
               QH + (uint32_t)(qrow * PADV + kk * 16 + qc8) * 2);

    float O[16][4];
#pragma unroll
    for (int i = 0; i < 16; i++)
#pragma unroll
        for (int j = 0; j < 4; j++) O[i][j] = 0.f;
    float m0 = -1e30f, m1 = -1e30f, l0 = 0.f, l1 = 0.f;

    const int nkt = qi + 1;
    for (int kt = 0; kt < nkt; kt++) {
        CP_WAIT0();          // KV(kt) resident
        __syncthreads();     // all warps done with KV(kt-1); visibility of KV(kt)
        if (kt + 1 < nkt) {
            stage_kv2(KV + (uint32_t)(((kt + 1) & 1) * KV_STAGE_B), base,
                      (kt + 1) * AKT, Ks, Vs, tid);
            CP_COMMIT();
        }
        const uint32_t cur = KV + (uint32_t)((kt & 1) * KV_STAGE_B);
        const uint32_t KsS = cur, VsS = cur + KV_TILE_B;

        // ---- scores: 16 n-frags over 128 keys ----
        float c[16][4];
#pragma unroll
        for (int i = 0; i < 16; i++)
#pragma unroll
            for (int j = 0; j < 4; j++) c[i][j] = 0.f;

#pragma unroll
        for (int kk = 0; kk < 8; kk++) {
            uint32_t qfl[4];
            ldm_x4(qfl[0], qfl[1], qfl[2], qfl[3],
                   QL + (uint32_t)(qrow * PADV + kk * 16 + qc8) * 2);
            const uint32_t kc = (uint32_t)(kk * 16 + ((lane >> 3) & 1) * 8) * 2;
#pragma unroll
            for (int nfp = 0; nfp < 8; nfp++) {
                const uint32_t nrow =
                    (uint32_t)(nfp * 16 + ((lane >> 4) << 3) + (lane & 7));
                uint32_t h0, h1, h2, h3;
                ldm_x4(h0, h1, h2, h3, KsS + nrow * (PADV * 2) + kc);
                uint32_t bA[2] = {h0, h1}, bB[2] = {h2, h3};
                mma_f16(c[2 * nfp],     qfh[kk], bA);
                mma_f16(c[2 * nfp],     qfl,     bA);
                mma_f16(c[2 * nfp + 1], qfh[kk], bB);
                mma_f16(c[2 * nfp + 1], qfl,     bB);
            }
        }

        // ---- causal mask (only the diagonal tile) ----
        if (kt == nkt - 1) {
            const int row0 = q0 + wid * 16 + (lane >> 2);
            const int col0 = kt * AKT + (lane & 3) * 2;
#pragma unroll
            for (int nf = 0; nf < 16; nf++) {
                const int cb = col0 + nf * 8;
                if (cb     > row0)     c[nf][0] = -1e30f;
                if (cb + 1 > row0)     c[nf][1] = -1e30f;
                if (cb     > row0 + 8) c[nf][2] = -1e30f;
                if (cb + 1 > row0 + 8) c[nf][3] = -1e30f;
            }
        }

        // ---- online softmax ----
        float rm0 = -1e30f, rm1 = -1e30f;
#pragma unroll
        for (int nf = 0; nf < 16; nf++) {
            rm0 = fmaxf(rm0, fmaxf(c[nf][0], c[nf][1]));
            rm1 = fmaxf(rm1, fmaxf(c[nf][2], c[nf][3]));
        }
        rm0 = fmaxf(rm0, __shfl_xor_sync(0xffffffffu, rm0, 1));
        rm0 = fmaxf(rm0, __shfl_xor_sync(0xffffffffu, rm0, 2));
        rm1 = fmaxf(rm1, __shfl_xor_sync(0xffffffffu, rm1, 1));
        rm1 = fmaxf(rm1, __shfl_xor_sync(0xffffffffu, rm1, 2));
        const float mn0 = fmaxf(m0, rm0), mn1 = fmaxf(m1, rm1);
        const float a0 = exp2p((m0 - mn0) * Cs);
        const float a1 = exp2p((m1 - mn1) * Cs);
        m0 = mn0; m1 = mn1;

        float rs0 = 0.f, rs1 = 0.f;
#pragma unroll
        for (int nf = 0; nf < 16; nf++) {
            c[nf][0] = exp2p((c[nf][0] - mn0) * Cs);
            c[nf][1] = exp2p((c[nf][1] - mn0) * Cs);
            c[nf][2] = exp2p((c[nf][2] - mn1) * Cs);
            c[nf][3] = exp2p((c[nf][3] - mn1) * Cs);
            rs0 += c[nf][0] + c[nf][1];
            rs1 += c[nf][2] + c[nf][3];
        }
        rs0 += __shfl_xor_sync(0xffffffffu, rs0, 1);
        rs0 += __shfl_xor_sync(0xffffffffu, rs0, 2);
        rs1 += __shfl_xor_sync(0xffffffffu, rs1, 1);
        rs1 += __shfl_xor_sync(0xffffffffu, rs1, 2);
        l0 = l0 * a0 + rs0;
        l1 = l1 * a1 + rs1;

#pragma unroll
        for (int i = 0; i < 16; i++) {
            O[i][0] *= a0; O[i][1] *= a0; O[i][2] *= a1; O[i][3] *= a1;
        }

        // ---- O += P @ V (P packed on the fly per 16-key group) ----
#pragma unroll
        for (int k2 = 0; k2 < 8; k2++) {
            uint32_t pah[4];
#pragma unroll
            for (int q = 0; q < 4; q++) {
                const int nf = 2 * k2 + (q >> 1);
                const int e  = (q & 1) * 2;
                pah[q] = packh(c[nf][e], c[nf][e + 1]);
            }
            const uint32_t vr =
                (uint32_t)(k2 * 16 + (lane & 7) + ((lane >> 3) & 1) * 8);
#pragma unroll
            for (int nfp = 0; nfp < 8; nfp++) {
                const uint32_t vc = (uint32_t)(nfp * 16 + ((lane >> 4) << 3));
                uint32_t h0, h1, h2, h3;
                ldm_x4t(h0, h1, h2, h3, VsS + (vr * PADV + vc) * 2);
                uint32_t bA[2] = {h0, h1}, bB[2] = {h2, h3};
                mma_f16(O[2 * nfp],     pah, bA);
                mma_f16(O[2 * nfp + 1], pah, bB);
            }
        }
    }

    // ---- epilogue: normalize, write AO single fp16 [B,S,H] ----
    const float inv0 = 1.f / l0, inv1 = 1.f / l1;
    const int srow0 = q0 + wid * 16 + (lane >> 2);
#pragma unroll
    for (int nf = 0; nf < 16; nf++) {
        const int col = hh * HDd + nf * 8 + (lane & 3) * 2;
        const size_t o0 = ((size_t)(bb * Ss) + srow0) * Hh + col;
        const size_t o1 = o0 + (size_t)8 * Hh;
        *(uint32_t*)&AOh[o0] = packh(O[nf][0] * inv0, O[nf][1] * inv0);
        *(uint32_t*)&AOh[o1] = packh(O[nf][2] * inv1, O[nf][3] * inv1);
    }
}

// ---------------------------------------------------------------------------
extern "C" void kernel_launch(void* const* d_in, const int* in_sizes, int n_in,
                              void* d_out, int out_size)
{
    (void)in_sizes; (void)n_in; (void)out_size;
    const float* x  = (const float*)d_in[0];
    const float* wq = (const float*)d_in[2];
    const float* bq = (const float*)d_in[3];
    const float* wk = (const float*)d_in[4];
    const float* bk = (const float*)d_in[5];
    const float* wv = (const float*)d_in[6];
    const float* bv = (const float*)d_in[7];
    const float* wo = (const float*)d_in[8];
    const float* bo = (const float*)d_in[9];
    float* out = (float*)d_out;

    __half *xh, *xl, *qh, *ql, *ks, *vs, *aoh, *wt;
    cudaGetSymbolAddress((void**)&xh,  g_Xh);
    cudaGetSymbolAddress((void**)&xl,  g_Xl);
    cudaGetSymbolAddress((void**)&qh,  g_Qh);
    cudaGetSymbolAddress((void**)&ql,  g_Ql);
    cudaGetSymbolAddress((void**)&ks,  g_Ks);
    cudaGetSymbolAddress((void**)&vs,  g_Vs);
    cudaGetSymbolAddress((void**)&aoh, g_AOh);
    cudaGetSymbolAddress((void**)&wt,  g_Wt);
    const size_t WSZ = (size_t)Hh * Hh;

    static bool attr_set = false;
    if (!attr_set) {
        cudaFuncSetAttribute(qkv_mma,
                             cudaFuncAttributeMaxDynamicSharedMemorySize, QKV_SMEM);
        cudaFuncSetAttribute(proj_mma,
                             cudaFuncAttributeMaxDynamicSharedMemorySize, PROJ_SMEM);
        cudaFuncSetAttribute(attn_mma,
                             cudaFuncAttributeMaxDynamicSharedMemorySize, ATT2_SMEM);
        attr_set = true;
    }

    const int N2 = Mm * Hh / 2;
    convert_split<<<(N2 + 255) / 256, 256>>>(
        (const float2*)x, (__half2*)xh, (__half2*)xl, N2);

    transpose_convert4<<<dim3(Hh / 32, Hh / 32, 4), dim3(32, 8)>>>(
        wq, wk, wv, wo, wt);

    // Q, K, V in one launch (z selects path)
    qkv_mma<<<dim3(Hh / 128, Mm / 128, 3), 256, QKV_SMEM>>>(
        xh, xl, wt, bq, bk, bv, qh, ql, ks, vs);

    attn_mma<<<dim3(Ss / AQT, NHh, Bb), 256, ATT2_SMEM>>>(qh, ql, ks, vs, aoh);

    proj_mma<<<dim3(Hh / 128, Mm / 128), 256, PROJ_SMEM>>>(
        aoh, wt + 3 * WSZ, bo, out);
}

// round 10
// speedup vs baseline: 1.0635x; 1.0635x over previous
#include <cuda_runtime.h>
#include <cuda_fp16.h>
#include <cstdint>

// Problem constants
#define Bb   2
#define Ss   2048
#define Hh   2048
#define NHh  16
#define HDd  128
#define Mm   4096   // B*S

// ---------------------------------------------------------------------------
// Scratch (device globals; no allocation allowed)
// ---------------------------------------------------------------------------
__device__ __half g_Xh[(size_t)Mm * Hh];
__device__ __half g_Xl[(size_t)Mm * Hh];
__device__ __half g_Qh[(size_t)Mm * Hh];
__device__ __half g_Ql[(size_t)Mm * Hh];
__device__ __half g_Ks[(size_t)Mm * Hh];
__device__ __half g_Vs[(size_t)Mm * Hh];
__device__ __half g_AOh[(size_t)Mm * Hh];
__device__ __half g_Wt[4][(size_t)Hh * Hh];

// ---------------------------------------------------------------------------
// PTX helpers (sm_80-level only: legal in compute_103 PTX)
// ---------------------------------------------------------------------------
__device__ __forceinline__ uint32_t smem_to_u32(const void* p) {
    uint32_t a;
    asm("{ .reg .u64 t; cvta.to.shared.u64 t, %1; cvt.u32.u64 %0, t; }"
        : "=r"(a) : "l"(p));
    return a;
}
__device__ __forceinline__ void cp16(uint32_t s, const void* g) {
    asm volatile("cp.async.cg.shared.global [%0], [%1], 16;" :: "r"(s), "l"(g));
}
#define CP_COMMIT() asm volatile("cp.async.commit_group;" ::: "memory")
#define CP_WAIT0()  asm volatile("cp.async.wait_group 0;" ::: "memory")
#define CP_WAIT1()  asm volatile("cp.async.wait_group 1;" ::: "memory")

__device__ __forceinline__ void ldm_x4(uint32_t& r0, uint32_t& r1, uint32_t& r2,
                                       uint32_t& r3, uint32_t addr) {
    asm volatile("ldmatrix.sync.aligned.m8n8.x4.shared.b16 {%0,%1,%2,%3}, [%4];"
                 : "=r"(r0), "=r"(r1), "=r"(r2), "=r"(r3) : "r"(addr));
}
__device__ __forceinline__ void ldm_x4t(uint32_t& r0, uint32_t& r1, uint32_t& r2,
                                        uint32_t& r3, uint32_t addr) {
    asm volatile("ldmatrix.sync.aligned.m8n8.x4.trans.shared.b16 {%0,%1,%2,%3}, [%4];"
                 : "=r"(r0), "=r"(r1), "=r"(r2), "=r"(r3) : "r"(addr));
}
__device__ __forceinline__ void ldm_x2(uint32_t& r0, uint32_t& r1, uint32_t addr) {
    asm volatile("ldmatrix.sync.aligned.m8n8.x2.shared.b16 {%0,%1}, [%2];"
                 : "=r"(r0), "=r"(r1) : "r"(addr));
}
__device__ __forceinline__ void mma_f16(float* c, const uint32_t* a, const uint32_t* b) {
    asm volatile("mma.sync.aligned.m16n8k16.row.col.f32.f16.f16.f32 "
                 "{%0,%1,%2,%3}, {%4,%5,%6,%7}, {%8,%9}, {%0,%1,%2,%3};"
                 : "+f"(c[0]), "+f"(c[1]), "+f"(c[2]), "+f"(c[3])
                 : "r"(a[0]), "r"(a[1]), "r"(a[2]), "r"(a[3]), "r"(b[0]), "r"(b[1]));
}

// Fast exp2 on the FMA pipe (deg-5 poly, f in [-0.5,0.5]); rel err ~2.4e-6.
__device__ __forceinline__ float exp2p(float t) {
    t = fmaxf(t, -120.f);
    float fn = t + 12582912.f;
    int   n  = __float_as_int(fn) - 0x4B400000;
    float f  = t - (fn - 12582912.f);
    float p  = 1.3333558146428443e-3f;
    p = fmaf(p, f, 9.6181291076284772e-3f);
    p = fmaf(p, f, 5.5504108664821580e-2f);
    p = fmaf(p, f, 2.4022650695910071e-1f);
    p = fmaf(p, f, 6.9314718055994531e-1f);
    p = fmaf(p, f, 1.0f);
    return p * __int_as_float((n + 127) << 23);
}

__device__ __forceinline__ uint32_t packh(float x, float y) {
    __half2 t = __floats2half2_rn(x, y);
    return *reinterpret_cast<uint32_t*>(&t);
}

// ---------------------------------------------------------------------------
// Conversions
// ---------------------------------------------------------------------------
__global__ void convert_split(const float2* __restrict__ X,
                              __half2* __restrict__ Xh,
                              __half2* __restrict__ Xl, int n2)
{
    int i = blockIdx.x * blockDim.x + threadIdx.x;
    if (i >= n2) return;
    float2 v = X[i];
    __half h0 = __float2half_rn(v.x);
    __half h1 = __float2half_rn(v.y);
    float r0 = v.x - __half2float(h0);
    float r1 = v.y - __half2float(h1);
    Xh[i] = __half2(h0, h1);
    Xl[i] = __half2(__float2half_rn(r0), __float2half_rn(r1));
}

// Fused transpose + convert for all 4 weights (z selects the matrix)
__global__ void transpose_convert4(const float* __restrict__ w0,
                                   const float* __restrict__ w1,
                                   const float* __restrict__ w2,
                                   const float* __restrict__ w3,
                                   __half* __restrict__ T)
{
    __shared__ float t[32][33];
    const float* W = (blockIdx.z == 0) ? w0 : (blockIdx.z == 1) ? w1
                   : (blockIdx.z == 2) ? w2 : w3;
    __half* Td = T + (size_t)blockIdx.z * Hh * Hh;
    const int n0 = blockIdx.x * 32, k0 = blockIdx.y * 32;
    const int tx = threadIdx.x, ty = threadIdx.y;   // (32, 8)
#pragma unroll
    for (int i = 0; i < 4; i++)
        t[ty + 8 * i][tx] = W[(size_t)(k0 + ty + 8 * i) * Hh + n0 + tx];
    __syncthreads();
#pragma unroll
    for (int i = 0; i < 4; i++)
        Td[(size_t)(n0 + ty + 8 * i) * Hh + k0 + tx] =
            __float2half_rn(t[tx][ty + 8 * i]);
}

// ---------------------------------------------------------------------------
// GEMM common geometry (R8-proven: BK=32, 3-stage pipeline, 2 CTAs/SM)
// ---------------------------------------------------------------------------
#define BKg   32
#define PADR  40
#define TILE_HALFS (128 * PADR)
#define TILE_B ((uint32_t)(TILE_HALFS * 2))
#define QKV_STAGE_B (3u * TILE_B)
#define QKV_SMEM (3 * 3 * (int)TILE_B)

__device__ __forceinline__ void stage_load_rt(uint32_t sb, bool asplit,
    const __half* __restrict__ Ah, const __half* __restrict__ Al,
    const __half* __restrict__ Bs, int bm, int bn, int k0, int tid)
{
    const int r = tid >> 1;
    const int c = (tid & 1) * 2;
#pragma unroll
    for (int cc = 0; cc < 2; cc++) {
        const uint32_t so = (uint32_t)(r * PADR + (c + cc) * 8) * 2;
        const size_t go = (size_t)k0 + (c + cc) * 8;
        cp16(sb + so, Ah + (size_t)(bm + r) * Hh + go);
        if (asplit)
            cp16(sb + TILE_B + so, Al + (size_t)(bm + r) * Hh + go);
        cp16(sb + 2 * TILE_B + so, Bs + (size_t)(bn + r) * Hh + go);
    }
}

// ---------------------------------------------------------------------------
// Merged QKV GEMM: z = 0 (Q: A split, hi/lo out), 1 (K: single, single out),
// 2 (V: single, single out). CTA 128x128, BK=32, 3-stage, 2 CTAs/SM.
// ---------------------------------------------------------------------------
__global__ __launch_bounds__(256, 2)
void qkv_mma(const __half* __restrict__ Xh, const __half* __restrict__ Xl,
             const __half* __restrict__ Wt,
             const float* __restrict__ bq, const float* __restrict__ bk,
             const float* __restrict__ bv,
             __half* __restrict__ Qh, __half* __restrict__ Ql,
             __half* __restrict__ Ks, __half* __restrict__ Vs)
{
    extern __shared__ __half smem[];
    const uint32_t sbase = smem_to_u32(smem);
    const int tid = threadIdx.x;
    const int wid = tid >> 5, lane = tid & 31;
    const int z = blockIdx.z;
    const bool asplit = (z == 0);          // K-split dropped (R9 numeric change kept)
    const __half* Bs = Wt + (size_t)z * Hh * Hh;
    const float* bias = (z == 0) ? bq : (z == 1) ? bk : bv;
    const int bn = blockIdx.x * 128, bm = blockIdx.y * 128;
    const int wm = (wid >> 2) * 64;
    const int wn = (wid & 3) * 32;

    float acc[4][4][4];
#pragma unroll
    for (int i = 0; i < 4; i++)
#pragma unroll
        for (int j = 0; j < 4; j++)
#pragma unroll
            for (int q = 0; q < 4; q++) acc[i][j][q] = 0.f;

    const int NIT = Hh / BKg;   // 64
    stage_load_rt(sbase, asplit, Xh, Xl, Bs, bm, bn, 0, tid);
    CP_COMMIT();
    stage_load_rt(sbase + QKV_STAGE_B, asplit, Xh, Xl, Bs, bm, bn, BKg, tid);
    CP_COMMIT();
    CP_WAIT1();
    __syncthreads();

    const int arow = lane & 15;
    const int acol8 = (lane >> 4) << 3;
    const int brow = lane & 7;
    const int bcol8 = ((lane >> 3) & 1) << 3;

    for (int kt = 0; kt < NIT; kt++) {
        const uint32_t sb = sbase + (uint32_t)(kt % 3) * QKV_STAGE_B;
        if (kt + 2 < NIT) {
            stage_load_rt(sbase + (uint32_t)((kt + 2) % 3) * QKV_STAGE_B,
                          asplit, Xh, Xl, Bs, bm, bn, (kt + 2) * BKg, tid);
            CP_COMMIT();
        }

#pragma unroll
        for (int ks = 0; ks < 2; ks++) {
            const int k0 = ks * 16;
            uint32_t bF[4][2];
#pragma unroll
            for (int ni = 0; ni < 4; ni++) {
                const uint32_t off =
                    (uint32_t)((wn + ni * 8 + brow) * PADR + k0 + bcol8) * 2;
                ldm_x2(bF[ni][0], bF[ni][1], sb + 2 * TILE_B + off);
            }
#pragma unroll
            for (int mi = 0; mi < 4; mi++) {
                const uint32_t off =
                    (uint32_t)((wm + mi * 16 + arow) * PADR + k0 + acol8) * 2;
                uint32_t aH[4];
                ldm_x4(aH[0], aH[1], aH[2], aH[3], sb + off);
#pragma unroll
                for (int ni = 0; ni < 4; ni++)
                    mma_f16(acc[mi][ni], aH, bF[ni]);
                if (asplit) {
                    uint32_t aL[4];
                    ldm_x4(aL[0], aL[1], aL[2], aL[3], sb + TILE_B + off);
#pragma unroll
                    for (int ni = 0; ni < 4; ni++)
                        mma_f16(acc[mi][ni], aL, bF[ni]);
                }
            }
        }

        if (kt + 1 < NIT) {
            if (kt + 2 < NIT) { CP_WAIT1(); } else { CP_WAIT0(); }
        }
        __syncthreads();
    }

    const int fr = lane >> 2;
    const int fc = (lane & 3) * 2;
#pragma unroll
    for (int mi = 0; mi < 4; mi++) {
#pragma unroll
        for (int ni = 0; ni < 4; ni++) {
            const int n0 = bn + wn + ni * 8 + fc;
            const float b0 = bias[n0], b1 = bias[n0 + 1];
#pragma unroll
            for (int half = 0; half < 2; half++) {
                const int m = bm + wm + mi * 16 + fr + half * 8;
                float v0 = acc[mi][ni][half * 2 + 0] + b0;
                float v1 = acc[mi][ni][half * 2 + 1] + b1;
                const int bb = m >> 11;
                const int ss = m & (Ss - 1);
                const int hh = n0 >> 7;
                const int dd = n0 & (HDd - 1);
                const size_t idx =
                    (((size_t)(bb * NHh + hh) * Ss) + ss) * HDd + dd;
                if (z == 0) {
                    __half h0 = __float2half_rn(v0);
                    __half h1 = __float2half_rn(v1);
                    float r0 = v0 - __half2float(h0);
                    float r1 = v1 - __half2float(h1);
                    *(__half2*)&Qh[idx] = __half2(h0, h1);
                    *(__half2*)&Ql[idx] = __half2(
                        __float2half_rn(r0), __float2half_rn(r1));
                } else if (z == 1) {
                    *(__half2*)&Ks[idx] = __floats2half2_rn(v0, v1);
                } else {
                    *(__half2*)&Vs[idx] = __floats2half2_rn(v0, v1);
                }
            }
        }
    }
}

// ---------------------------------------------------------------------------
// Output projection GEMM: C[M,N] = A @ B^T + bias, fp32 out, single-A.
// ---------------------------------------------------------------------------
__global__ __launch_bounds__(256, 2)
void proj_mma(const __half* __restrict__ Ah, const __half* __restrict__ Bw,
              const float* __restrict__ bias, float* __restrict__ Cf)
{
    extern __shared__ __half smem[];
    const uint32_t sbase = smem_to_u32(smem);
    const int tid = threadIdx.x;
    const int wid = tid >> 5, lane = tid & 31;
    const int bn = blockIdx.x * 128, bm = blockIdx.y * 128;
    const int wm = (wid >> 2) * 64;
    const int wn = (wid & 3) * 32;

    float acc[4][4][4];
#pragma unroll
    for (int i = 0; i < 4; i++)
#pragma unroll
        for (int j = 0; j < 4; j++)
#pragma unroll
            for (int q = 0; q < 4; q++) acc[i][j][q] = 0.f;

    const int NIT = Hh / BKg;
    stage_load_rt(sbase, false, Ah, nullptr, Bw, bm, bn, 0, tid);
    CP_COMMIT();
    stage_load_rt(sbase + QKV_STAGE_B, false, Ah, nullptr, Bw, bm, bn, BKg, tid);
    CP_COMMIT();
    CP_WAIT1();
    __syncthreads();

    const int arow = lane & 15;
    const int acol8 = (lane >> 4) << 3;
    const int brow = lane & 7;
    const int bcol8 = ((lane >> 3) & 1) << 3;

    for (int kt = 0; kt < NIT; kt++) {
        const uint32_t sb = sbase + (uint32_t)(kt % 3) * QKV_STAGE_B;
        if (kt + 2 < NIT) {
            stage_load_rt(sbase + (uint32_t)((kt + 2) % 3) * QKV_STAGE_B,
                          false, Ah, nullptr, Bw, bm, bn, (kt + 2) * BKg, tid);
            CP_COMMIT();
        }
#pragma unroll
        for (int ks = 0; ks < 2; ks++) {
            const int k0 = ks * 16;
            uint32_t bF[4][2];
#pragma unroll
            for (int ni = 0; ni < 4; ni++) {
                const uint32_t off =
                    (uint32_t)((wn + ni * 8 + brow) * PADR + k0 + bcol8) * 2;
                ldm_x2(bF[ni][0], bF[ni][1], sb + 2 * TILE_B + off);
            }
#pragma unroll
            for (int mi = 0; mi < 4; mi++) {
                const uint32_t off =
                    (uint32_t)((wm + mi * 16 + arow) * PADR + k0 + acol8) * 2;
                uint32_t aH[4];
                ldm_x4(aH[0], aH[1], aH[2], aH[3], sb + off);
#pragma unroll
                for (int ni = 0; ni < 4; ni++)
                    mma_f16(acc[mi][ni], aH, bF[ni]);
            }
        }
        if (kt + 1 < NIT) {
            if (kt + 2 < NIT) { CP_WAIT1(); } else { CP_WAIT0(); }
        }
        __syncthreads();
    }

    const int fr = lane >> 2;
    const int fc = (lane & 3) * 2;
#pragma unroll
    for (int mi = 0; mi < 4; mi++) {
#pragma unroll
        for (int ni = 0; ni < 4; ni++) {
            const int n0 = bn + wn + ni * 8 + fc;
            const float b0 = bias[n0], b1 = bias[n0 + 1];
#pragma unroll
            for (int half = 0; half < 2; half++) {
                const int m = bm + wm + mi * 16 + fr + half * 8;
                float2 w;
                w.x = acc[mi][ni][half * 2 + 0] + b0;
                w.y = acc[mi][ni][half * 2 + 1] + b1;
                *(float2*)&Cf[(size_t)m * Hh + n0] = w;
            }
        }
    }
}

// ---------------------------------------------------------------------------
// HMMA fp16 flash attention: AKT=128, Q_lo resident in smem, single sync/kt.
// CTA: 128 q rows, 8 warps x 16 rows. KV double-buffered cp.async.
// ---------------------------------------------------------------------------
#define AQT 128
#define AKT 128
#define PADV 136
#define Q_TILE_B   (AQT * PADV * 2)        // 34816 bytes (hi), same for lo
#define KV_TILE_B  (AKT * PADV * 2)        // 34816 bytes
#define KV_STAGE_B (2 * KV_TILE_B)         // K, V = 69632 bytes
#define ATT_Q_B    (2 * Q_TILE_B)          // 69632 bytes
#define ATT2_SMEM  (ATT_Q_B + 2 * KV_STAGE_B)   // 208896 bytes

__device__ __forceinline__ void stage_kv2(uint32_t dst, size_t base, int kn0,
    const __half* __restrict__ Ks, const __half* __restrict__ Vs, int tid)
{
#pragma unroll
    for (int i = 0; i < 8; i++) {
        const int idx = i * 256 + tid;
        const int row = idx >> 4, ch = idx & 15;
        const uint32_t so = (uint32_t)(row * PADV + ch * 8) * 2;
        const size_t go = base + (size_t)(kn0 + row) * HDd + ch * 8;
        cp16(dst +             so, Ks + go);
        cp16(dst + KV_TILE_B + so, Vs + go);
    }
}

__global__ __launch_bounds__(256, 1)
void attn_mma(const __half* __restrict__ Qh, const __half* __restrict__ Ql,
              const __half* __restrict__ Ks, const __half* __restrict__ Vs,
              __half* __restrict__ AOh)
{
    extern __shared__ __half asmem[];
    const uint32_t sb = smem_to_u32(asmem);
    const uint32_t QH = sb, QL = sb + Q_TILE_B, KV = sb + ATT_Q_B;
    const int tid = threadIdx.x, wid = tid >> 5, lane = tid & 31;
    const int qi = (int)gridDim.x - 1 - (int)blockIdx.x;   // big tiles first
    const int hh = blockIdx.y, bb = blockIdx.z;
    const size_t base = ((size_t)(bb * NHh + hh)) * Ss * HDd;
    const int q0 = qi * AQT;
    const float Cs = 0.12751745210319466f;   // 128^-0.5 * log2(e)

    const int qrow = wid * 16 + (lane & 15);
    const int qc8 = (lane >> 4) << 3;

    // ---- prologue: Q hi+lo to resident smem; KV tile 0 in flight ----
#pragma unroll
    for (int i = 0; i < 8; i++) {
        const int idx = i * 256 + tid;
        const int row = idx >> 4, ch = idx & 15;
        const uint32_t so = (uint32_t)(row * PADV + ch * 8) * 2;
        const size_t go = base + (size_t)(q0 + row) * HDd + ch * 8;
        cp16(QH + so, Qh + go);
        cp16(QL + so, Ql + go);
    }
    CP_COMMIT();
    stage_kv2(KV, base, 0, Ks, Vs, tid);
    CP_COMMIT();
    CP_WAIT1();          // Q ready
    __syncthreads();

    uint32_t qfh[8][4];
#pragma unroll
    for (int kk = 0; kk < 8; kk++)
        ldm_x4(qfh[kk][0], qfh[kk][1], qfh[kk][2], qfh[kk][3],
               QH + (uint32_t)(qrow * PADV + kk * 16 + qc8) * 2);

    float O[16][4];
#pragma unroll
    for (int i = 0; i < 16; i++)
#pragma unroll
        for (int j = 0; j < 4; j++) O[i][j] = 0.f;
    float m0 = -1e30f, m1 = -1e30f, l0 = 0.f, l1 = 0.f;

    const int nkt = qi + 1;
    for (int kt = 0; kt < nkt; kt++) {
        CP_WAIT0();          // KV(kt) resident
        __syncthreads();     // all warps done with KV(kt-1); visibility of KV(kt)
        if (kt + 1 < nkt) {
            stage_kv2(KV + (uint32_t)(((kt + 1) & 1) * KV_STAGE_B), base,
                      (kt + 1) * AKT, Ks, Vs, tid);
            CP_COMMIT();
        }
        const uint32_t cur = KV + (uint32_t)((kt & 1) * KV_STAGE_B);
        const uint32_t KsS = cur, VsS = cur + KV_TILE_B;

        // ---- scores: 16 n-frags over 128 keys ----
        float c[16][4];
#pragma unroll
        for (int i = 0; i < 16; i++)
#pragma unroll
            for (int j = 0; j < 4; j++) c[i][j] = 0.f;

#pragma unroll
        for (int kk = 0; kk < 8; kk++) {
            uint32_t qfl[4];
            ldm_x4(qfl[0], qfl[1], qfl[2], qfl[3],
                   QL + (uint32_t)(qrow * PADV + kk * 16 + qc8) * 2);
            const uint32_t kc = (uint32_t)(kk * 16 + ((lane >> 3) & 1) * 8) * 2;
#pragma unroll
            for (int nfp = 0; nfp < 8; nfp++) {
                const uint32_t nrow =
                    (uint32_t)(nfp * 16 + ((lane >> 4) << 3) + (lane & 7));
                uint32_t h0, h1, h2, h3;
                ldm_x4(h0, h1, h2, h3, KsS + nrow * (PADV * 2) + kc);
                uint32_t bA[2] = {h0, h1}, bB[2] = {h2, h3};
                mma_f16(c[2 * nfp],     qfh[kk], bA);
                mma_f16(c[2 * nfp],     qfl,     bA);
                mma_f16(c[2 * nfp + 1], qfh[kk], bB);
                mma_f16(c[2 * nfp + 1], qfl,     bB);
            }
        }

        // ---- causal mask (only the diagonal tile) ----
        if (kt == nkt - 1) {
            const int row0 = q0 + wid * 16 + (lane >> 2);
            const int col0 = kt * AKT + (lane & 3) * 2;
#pragma unroll
            for (int nf = 0; nf < 16; nf++) {
                const int cb = col0 + nf * 8;
                if (cb     > row0)     c[nf][0] = -1e30f;
                if (cb + 1 > row0)     c[nf][1] = -1e30f;
                if (cb     > row0 + 8) c[nf][2] = -1e30f;
                if (cb + 1 > row0 + 8) c[nf][3] = -1e30f;
            }
        }

        // ---- online softmax ----
        float rm0 = -1e30f, rm1 = -1e30f;
#pragma unroll
        for (int nf = 0; nf < 16; nf++) {
            rm0 = fmaxf(rm0, fmaxf(c[nf][0], c[nf][1]));
            rm1 = fmaxf(rm1, fmaxf(c[nf][2], c[nf][3]));
        }
        rm0 = fmaxf(rm0, __shfl_xor_sync(0xffffffffu, rm0, 1));
        rm0 = fmaxf(rm0, __shfl_xor_sync(0xffffffffu, rm0, 2));
        rm1 = fmaxf(rm1, __shfl_xor_sync(0xffffffffu, rm1, 1));
        rm1 = fmaxf(rm1, __shfl_xor_sync(0xffffffffu, rm1, 2));
        const float mn0 = fmaxf(m0, rm0), mn1 = fmaxf(m1, rm1);
        const float a0 = exp2p((m0 - mn0) * Cs);
        const float a1 = exp2p((m1 - mn1) * Cs);
        m0 = mn0; m1 = mn1;

        float rs0 = 0.f, rs1 = 0.f;
#pragma unroll
        for (int nf = 0; nf < 16; nf++) {
            c[nf][0] = exp2p((c[nf][0] - mn0) * Cs);
            c[nf][1] = exp2p((c[nf][1] - mn0) * Cs);
            c[nf][2] = exp2p((c[nf][2] - mn1) * Cs);
            c[nf][3] = exp2p((c[nf][3] - mn1) * Cs);
            rs0 += c[nf][0] + c[nf][1];
            rs1 += c[nf][2] + c[nf][3];
        }
        rs0 += __shfl_xor_sync(0xffffffffu, rs0, 1);
        rs0 += __shfl_xor_sync(0xffffffffu, rs0, 2);
        rs1 += __shfl_xor_sync(0xffffffffu, rs1, 1);
        rs1 += __shfl_xor_sync(0xffffffffu, rs1, 2);
        l0 = l0 * a0 + rs0;
        l1 = l1 * a1 + rs1;

#pragma unroll
        for (int i = 0; i < 16; i++) {
            O[i][0] *= a0; O[i][1] *= a0; O[i][2] *= a1; O[i][3] *= a1;
        }

        // ---- O += P @ V (P packed on the fly per 16-key group) ----
#pragma unroll
        for (int k2 = 0; k2 < 8; k2++) {
            uint32_t pah[4];
#pragma unroll
            for (int q = 0; q < 4; q++) {
                const int nf = 2 * k2 + (q >> 1);
                const int e  = (q & 1) * 2;
                pah[q] = packh(c[nf][e], c[nf][e + 1]);
            }
            const uint32_t vr =
                (uint32_t)(k2 * 16 + (lane & 7) + ((lane >> 3) & 1) * 8);
#pragma unroll
            for (int nfp = 0; nfp < 8; nfp++) {
                const uint32_t vc = (uint32_t)(nfp * 16 + ((lane >> 4) << 3));
                uint32_t h0, h1, h2, h3;
                ldm_x4t(h0, h1, h2, h3, VsS + (vr * PADV + vc) * 2);
                uint32_t bA[2] = {h0, h1}, bB[2] = {h2, h3};
                mma_f16(O[2 * nfp],     pah, bA);
                mma_f16(O[2 * nfp + 1], pah, bB);
            }
        }
    }

    // ---- epilogue: normalize, write AO single fp16 [B,S,H] ----
    const float inv0 = 1.f / l0, inv1 = 1.f / l1;
    const int srow0 = q0 + wid * 16 + (lane >> 2);
#pragma unroll
    for (int nf = 0; nf < 16; nf++) {
        const int col = hh * HDd + nf * 8 + (lane & 3) * 2;
        const size_t o0 = ((size_t)(bb * Ss) + srow0) * Hh + col;
        const size_t o1 = o0 + (size_t)8 * Hh;
        *(uint32_t*)&AOh[o0] = packh(O[nf][0] * inv0, O[nf][1] * inv0);
        *(uint32_t*)&AOh[o1] = packh(O[nf][2] * inv1, O[nf][3] * inv1);
    }
}

// ---------------------------------------------------------------------------
extern "C" void kernel_launch(void* const* d_in, const int* in_sizes, int n_in,
                              void* d_out, int out_size)
{
    (void)in_sizes; (void)n_in; (void)out_size;
    const float* x  = (const float*)d_in[0];
    const float* wq = (const float*)d_in[2];
    const float* bq = (const float*)d_in[3];
    const float* wk = (const float*)d_in[4];
    const float* bk = (const float*)d_in[5];
    const float* wv = (const float*)d_in[6];
    const float* bv = (const float*)d_in[7];
    const float* wo = (const float*)d_in[8];
    const float* bo = (const float*)d_in[9];
    float* out = (float*)d_out;

    __half *xh, *xl, *qh, *ql, *ks, *vs, *aoh, *wt;
    cudaGetSymbolAddress((void**)&xh,  g_Xh);
    cudaGetSymbolAddress((void**)&xl,  g_Xl);
    cudaGetSymbolAddress((void**)&qh,  g_Qh);
    cudaGetSymbolAddress((void**)&ql,  g_Ql);
    cudaGetSymbolAddress((void**)&ks,  g_Ks);
    cudaGetSymbolAddress((void**)&vs,  g_Vs);
    cudaGetSymbolAddress((void**)&aoh, g_AOh);
    cudaGetSymbolAddress((void**)&wt,  g_Wt);
    const size_t WSZ = (size_t)Hh * Hh;

    static bool attr_set = false;
    if (!attr_set) {
        cudaFuncSetAttribute(qkv_mma,
                             cudaFuncAttributeMaxDynamicSharedMemorySize, QKV_SMEM);
        cudaFuncSetAttribute(proj_mma,
                             cudaFuncAttributeMaxDynamicSharedMemorySize, QKV_SMEM);
        cudaFuncSetAttribute(attn_mma,
                             cudaFuncAttributeMaxDynamicSharedMemorySize, ATT2_SMEM);
        attr_set = true;
    }

    const int N2 = Mm * Hh / 2;
    convert_split<<<(N2 + 255) / 256, 256>>>(
        (const float2*)x, (__half2*)xh, (__half2*)xl, N2);

    transpose_convert4<<<dim3(Hh / 32, Hh / 32, 4), dim3(32, 8)>>>(
        wq, wk, wv, wo, wt);

    // Q, K, V in one launch (z selects path)
    qkv_mma<<<dim3(Hh / 128, Mm / 128, 3), 256, QKV_SMEM>>>(
        xh, xl, wt, bq, bk, bv, qh, ql, ks, vs);

    attn_mma<<<dim3(Ss / AQT, NHh, Bb), 256, ATT2_SMEM>>>(qh, ql, ks, vs, aoh);

    proj_mma<<<dim3(Hh / 128, Mm / 128), 256, QKV_SMEM>>>(
        aoh, wt + 3 * WSZ, bo, out);
}

// round 11
// speedup vs baseline: 1.3387x; 1.2588x over previous
#include <cuda_runtime.h>
#include <cuda_fp16.h>
#include <cstdint>

// Problem constants
#define Bb   2
#define Ss   2048
#define Hh   2048
#define NHh  16
#define HDd  128
#define Mm   4096   // B*S

// ---------------------------------------------------------------------------
// Scratch (device globals; no allocation allowed)
// ---------------------------------------------------------------------------
__device__ __half g_Xs[(size_t)Mm * Hh];
__device__ __half g_Qs[(size_t)Mm * Hh];
__device__ __half g_Ks[(size_t)Mm * Hh];
__device__ __half g_Vs[(size_t)Mm * Hh];
__device__ __half g_AOh[(size_t)Mm * Hh];
__device__ __half g_Wt[4][(size_t)Hh * Hh];

// ---------------------------------------------------------------------------
// PTX helpers (sm_80-level only: legal in compute_103 PTX)
// ---------------------------------------------------------------------------
__device__ __forceinline__ uint32_t smem_to_u32(const void* p) {
    uint32_t a;
    asm("{ .reg .u64 t; cvta.to.shared.u64 t, %1; cvt.u32.u64 %0, t; }"
        : "=r"(a) : "l"(p));
    return a;
}
__device__ __forceinline__ void cp16(uint32_t s, const void* g) {
    asm volatile("cp.async.cg.shared.global [%0], [%1], 16;" :: "r"(s), "l"(g));
}
#define CP_COMMIT() asm volatile("cp.async.commit_group;" ::: "memory")
#define CP_WAIT0()  asm volatile("cp.async.wait_group 0;" ::: "memory")
#define CP_WAIT1()  asm volatile("cp.async.wait_group 1;" ::: "memory")

__device__ __forceinline__ void ldm_x4(uint32_t& r0, uint32_t& r1, uint32_t& r2,
                                       uint32_t& r3, uint32_t addr) {
    asm volatile("ldmatrix.sync.aligned.m8n8.x4.shared.b16 {%0,%1,%2,%3}, [%4];"
                 : "=r"(r0), "=r"(r1), "=r"(r2), "=r"(r3) : "r"(addr));
}
__device__ __forceinline__ void ldm_x4t(uint32_t& r0, uint32_t& r1, uint32_t& r2,
                                        uint32_t& r3, uint32_t addr) {
    asm volatile("ldmatrix.sync.aligned.m8n8.x4.trans.shared.b16 {%0,%1,%2,%3}, [%4];"
                 : "=r"(r0), "=r"(r1), "=r"(r2), "=r"(r3) : "r"(addr));
}
__device__ __forceinline__ void ldm_x2(uint32_t& r0, uint32_t& r1, uint32_t addr) {
    asm volatile("ldmatrix.sync.aligned.m8n8.x2.shared.b16 {%0,%1}, [%2];"
                 : "=r"(r0), "=r"(r1) : "r"(addr));
}
__device__ __forceinline__ void mma_f16(float* c, const uint32_t* a, const uint32_t* b) {
    asm volatile("mma.sync.aligned.m16n8k16.row.col.f32.f16.f16.f32 "
                 "{%0,%1,%2,%3}, {%4,%5,%6,%7}, {%8,%9}, {%0,%1,%2,%3};"
                 : "+f"(c[0]), "+f"(c[1]), "+f"(c[2]), "+f"(c[3])
                 : "r"(a[0]), "r"(a[1]), "r"(a[2]), "r"(a[3]), "r"(b[0]), "r"(b[1]));
}

// Fast exp2 on the FMA pipe (deg-5 poly, f in [-0.5,0.5]); rel err ~2.4e-6.
__device__ __forceinline__ float exp2p(float t) {
    t = fmaxf(t, -120.f);
    float fn = t + 12582912.f;
    int   n  = __float_as_int(fn) - 0x4B400000;
    float f  = t - (fn - 12582912.f);
    float p  = 1.3333558146428443e-3f;
    p = fmaf(p, f, 9.6181291076284772e-3f);
    p = fmaf(p, f, 5.5504108664821580e-2f);
    p = fmaf(p, f, 2.4022650695910071e-1f);
    p = fmaf(p, f, 6.9314718055994531e-1f);
    p = fmaf(p, f, 1.0f);
    return p * __int_as_float((n + 127) << 23);
}

__device__ __forceinline__ uint32_t packh(float x, float y) {
    __half2 t = __floats2half2_rn(x, y);
    return *reinterpret_cast<uint32_t*>(&t);
}

// ---------------------------------------------------------------------------
// Conversions
// ---------------------------------------------------------------------------
__global__ void convert_half(const float2* __restrict__ X,
                             __half2* __restrict__ Xs, int n2)
{
    int i = blockIdx.x * blockDim.x + threadIdx.x;
    if (i >= n2) return;
    float2 v = X[i];
    Xs[i] = __floats2half2_rn(v.x, v.y);
}

// Fused transpose + convert for all 4 weights (z selects the matrix)
__global__ void transpose_convert4(const float* __restrict__ w0,
                                   const float* __restrict__ w1,
                                   const float* __restrict__ w2,
                                   const float* __restrict__ w3,
                                   __half* __restrict__ T)
{
    __shared__ float t[32][33];
    const float* W = (blockIdx.z == 0) ? w0 : (blockIdx.z == 1) ? w1
                   : (blockIdx.z == 2) ? w2 : w3;
    __half* Td = T + (size_t)blockIdx.z * Hh * Hh;
    const int n0 = blockIdx.x * 32, k0 = blockIdx.y * 32;
    const int tx = threadIdx.x, ty = threadIdx.y;   // (32, 8)
#pragma unroll
    for (int i = 0; i < 4; i++)
        t[ty + 8 * i][tx] = W[(size_t)(k0 + ty + 8 * i) * Hh + n0 + tx];
    __syncthreads();
#pragma unroll
    for (int i = 0; i < 4; i++)
        Td[(size_t)(n0 + ty + 8 * i) * Hh + k0 + tx] =
            __float2half_rn(t[tx][ty + 8 * i]);
}

// ---------------------------------------------------------------------------
// GEMM common geometry: BK=32, 3-stage pipeline, uniform single-A, 2 CTAs/SM.
// Stage layout: [A tile][B tile], each 128x32 halfs padded to 40/row.
// ---------------------------------------------------------------------------
#define BKg   32
#define PADR  40
#define TILE_HALFS (128 * PADR)
#define TILE_B ((uint32_t)(TILE_HALFS * 2))   // 10240 bytes
#define STAGE_B (2u * TILE_B)                 // 20480 bytes
#define GEMM_SMEM (3 * 2 * (int)TILE_B)       // 61440 bytes

__device__ __forceinline__ void stage_load(uint32_t sb,
    const __half* __restrict__ As, const __half* __restrict__ Bs,
    int bm, int bn, int k0, int tid)
{
    const int r = tid >> 1;
    const int c = (tid & 1) * 2;
#pragma unroll
    for (int cc = 0; cc < 2; cc++) {
        const uint32_t so = (uint32_t)(r * PADR + (c + cc) * 8) * 2;
        const size_t go = (size_t)k0 + (c + cc) * 8;
        cp16(sb + so,          As + (size_t)(bm + r) * Hh + go);
        cp16(sb + TILE_B + so, Bs + (size_t)(bn + r) * Hh + go);
    }
}

// ---------------------------------------------------------------------------
// Merged QKV GEMM: uniform single-MMA; z selects weight/bias/output.
// CTA 128x128, BK=32, 3-stage, 2 CTAs/SM. Head-major fp16 out.
// ---------------------------------------------------------------------------
__global__ __launch_bounds__(256, 2)
void qkv_mma(const __half* __restrict__ Xs, const __half* __restrict__ Wt,
             const float* __restrict__ bq, const float* __restrict__ bk,
             const float* __restrict__ bv,
             __half* __restrict__ Qs, __half* __restrict__ Ks,
             __half* __restrict__ Vs)
{
    extern __shared__ __half smem[];
    const uint32_t sbase = smem_to_u32(smem);
    const int tid = threadIdx.x;
    const int wid = tid >> 5, lane = tid & 31;
    const int z = blockIdx.z;
    const __half* Bs = Wt + (size_t)z * Hh * Hh;
    const float* bias = (z == 0) ? bq : (z == 1) ? bk : bv;
    __half* Co = (z == 0) ? Qs : (z == 1) ? Ks : Vs;
    const int bn = blockIdx.x * 128, bm = blockIdx.y * 128;
    const int wm = (wid >> 2) * 64;
    const int wn = (wid & 3) * 32;

    float acc[4][4][4];
#pragma unroll
    for (int i = 0; i < 4; i++)
#pragma unroll
        for (int j = 0; j < 4; j++)
#pragma unroll
            for (int q = 0; q < 4; q++) acc[i][j][q] = 0.f;

    const int NIT = Hh / BKg;   // 64
    stage_load(sbase, Xs, Bs, bm, bn, 0, tid);
    CP_COMMIT();
    stage_load(sbase + STAGE_B, Xs, Bs, bm, bn, BKg, tid);
    CP_COMMIT();
    CP_WAIT1();
    __syncthreads();

    const int arow = lane & 15;
    const int acol8 = (lane >> 4) << 3;
    const int brow = lane & 7;
    const int bcol8 = ((lane >> 3) & 1) << 3;

    for (int kt = 0; kt < NIT; kt++) {
        const uint32_t sb = sbase + (uint32_t)(kt % 3) * STAGE_B;
        if (kt + 2 < NIT) {
            stage_load(sbase + (uint32_t)((kt + 2) % 3) * STAGE_B,
                       Xs, Bs, bm, bn, (kt + 2) * BKg, tid);
            CP_COMMIT();
        }

#pragma unroll
        for (int ks = 0; ks < 2; ks++) {
            const int k0 = ks * 16;
            uint32_t bF[4][2];
#pragma unroll
            for (int ni = 0; ni < 4; ni++) {
                const uint32_t off =
                    (uint32_t)((wn + ni * 8 + brow) * PADR + k0 + bcol8) * 2;
                ldm_x2(bF[ni][0], bF[ni][1], sb + TILE_B + off);
            }
#pragma unroll
            for (int mi = 0; mi < 4; mi++) {
                const uint32_t off =
                    (uint32_t)((wm + mi * 16 + arow) * PADR + k0 + acol8) * 2;
                uint32_t aH[4];
                ldm_x4(aH[0], aH[1], aH[2], aH[3], sb + off);
#pragma unroll
                for (int ni = 0; ni < 4; ni++)
                    mma_f16(acc[mi][ni], aH, bF[ni]);
            }
        }

        if (kt + 1 < NIT) {
            if (kt + 2 < NIT) { CP_WAIT1(); } else { CP_WAIT0(); }
        }
        __syncthreads();
    }

    const int fr = lane >> 2;
    const int fc = (lane & 3) * 2;
#pragma unroll
    for (int mi = 0; mi < 4; mi++) {
#pragma unroll
        for (int ni = 0; ni < 4; ni++) {
            const int n0 = bn + wn + ni * 8 + fc;
            const float b0 = bias[n0], b1 = bias[n0 + 1];
#pragma unroll
            for (int half = 0; half < 2; half++) {
                const int m = bm + wm + mi * 16 + fr + half * 8;
                float v0 = acc[mi][ni][half * 2 + 0] + b0;
                float v1 = acc[mi][ni][half * 2 + 1] + b1;
                const int bb = m >> 11;
                const int ss = m & (Ss - 1);
                const int hh = n0 >> 7;
                const int dd = n0 & (HDd - 1);
                const size_t idx =
                    (((size_t)(bb * NHh + hh) * Ss) + ss) * HDd + dd;
                *(__half2*)&Co[idx] = __floats2half2_rn(v0, v1);
            }
        }
    }
}

// ---------------------------------------------------------------------------
// Output projection GEMM: C[M,N] = A @ B^T + bias, fp32 row-major out.
// ---------------------------------------------------------------------------
__global__ __launch_bounds__(256, 2)
void proj_mma(const __half* __restrict__ Ah, const __half* __restrict__ Bw,
              const float* __restrict__ bias, float* __restrict__ Cf)
{
    extern __shared__ __half smem[];
    const uint32_t sbase = smem_to_u32(smem);
    const int tid = threadIdx.x;
    const int wid = tid >> 5, lane = tid & 31;
    const int bn = blockIdx.x * 128, bm = blockIdx.y * 128;
    const int wm = (wid >> 2) * 64;
    const int wn = (wid & 3) * 32;

    float acc[4][4][4];
#pragma unroll
    for (int i = 0; i < 4; i++)
#pragma unroll
        for (int j = 0; j < 4; j++)
#pragma unroll
            for (int q = 0; q < 4; q++) acc[i][j][q] = 0.f;

    const int NIT = Hh / BKg;
    stage_load(sbase, Ah, Bw, bm, bn, 0, tid);
    CP_COMMIT();
    stage_load(sbase + STAGE_B, Ah, Bw, bm, bn, BKg, tid);
    CP_COMMIT();
    CP_WAIT1();
    __syncthreads();

    const int arow = lane & 15;
    const int acol8 = (lane >> 4) << 3;
    const int brow = lane & 7;
    const int bcol8 = ((lane >> 3) & 1) << 3;

    for (int kt = 0; kt < NIT; kt++) {
        const uint32_t sb = sbase + (uint32_t)(kt % 3) * STAGE_B;
        if (kt + 2 < NIT) {
            stage_load(sbase + (uint32_t)((kt + 2) % 3) * STAGE_B,
                       Ah, Bw, bm, bn, (kt + 2) * BKg, tid);
            CP_COMMIT();
        }
#pragma unroll
        for (int ks = 0; ks < 2; ks++) {
            const int k0 = ks * 16;
            uint32_t bF[4][2];
#pragma unroll
            for (int ni = 0; ni < 4; ni++) {
                const uint32_t off =
                    (uint32_t)((wn + ni * 8 + brow) * PADR + k0 + bcol8) * 2;
                ldm_x2(bF[ni][0], bF[ni][1], sb + TILE_B + off);
            }
#pragma unroll
            for (int mi = 0; mi < 4; mi++) {
                const uint32_t off =
                    (uint32_t)((wm + mi * 16 + arow) * PADR + k0 + acol8) * 2;
                uint32_t aH[4];
                ldm_x4(aH[0], aH[1], aH[2], aH[3], sb + off);
#pragma unroll
                for (int ni = 0; ni < 4; ni++)
                    mma_f16(acc[mi][ni], aH, bF[ni]);
            }
        }
        if (kt + 1 < NIT) {
            if (kt + 2 < NIT) { CP_WAIT1(); } else { CP_WAIT0(); }
        }
        __syncthreads();
    }

    const int fr = lane >> 2;
    const int fc = (lane & 3) * 2;
#pragma unroll
    for (int mi = 0; mi < 4; mi++) {
#pragma unroll
        for (int ni = 0; ni < 4; ni++) {
            const int n0 = bn + wn + ni * 8 + fc;
            const float b0 = bias[n0], b1 = bias[n0 + 1];
#pragma unroll
            for (int half = 0; half < 2; half++) {
                const int m = bm + wm + mi * 16 + fr + half * 8;
                float2 w;
                w.x = acc[mi][ni][half * 2 + 0] + b0;
                w.y = acc[mi][ni][half * 2 + 1] + b1;
                *(float2*)&Cf[(size_t)m * Hh + n0] = w;
            }
        }
    }
}

// ---------------------------------------------------------------------------
// HMMA fp16 flash attention: single-fp16 Q/K/V, AKT=128, single sync/kt.
// CTA: 128 q rows, 8 warps x 16 rows. KV double-buffered cp.async.
// ---------------------------------------------------------------------------
#define AQT 128
#define AKT 128
#define PADV 136
#define Q_TILE_B   (AQT * PADV * 2)        // 34816 bytes
#define KV_TILE_B  (AKT * PADV * 2)        // 34816 bytes
#define KV_STAGE_B (2 * KV_TILE_B)         // K, V = 69632 bytes
#define ATT2_SMEM  (Q_TILE_B + 2 * KV_STAGE_B)   // 174080 bytes

__device__ __forceinline__ void stage_kv2(uint32_t dst, size_t base, int kn0,
    const __half* __restrict__ Ks, const __half* __restrict__ Vs, int tid)
{
#pragma unroll
    for (int i = 0; i < 8; i++) {
        const int idx = i * 256 + tid;
        const int row = idx >> 4, ch = idx & 15;
        const uint32_t so = (uint32_t)(row * PADV + ch * 8) * 2;
        const size_t go = base + (size_t)(kn0 + row) * HDd + ch * 8;
        cp16(dst +             so, Ks + go);
        cp16(dst + KV_TILE_B + so, Vs + go);
    }
}

__global__ __launch_bounds__(256, 1)
void attn_mma(const __half* __restrict__ Qs, const __half* __restrict__ Ks,
              const __half* __restrict__ Vs, __half* __restrict__ AOh)
{
    extern __shared__ __half asmem[];
    const uint32_t sb = smem_to_u32(asmem);
    const uint32_t QH = sb, KV = sb + Q_TILE_B;
    const int tid = threadIdx.x, wid = tid >> 5, lane = tid & 31;
    const int qi = (int)gridDim.x - 1 - (int)blockIdx.x;   // big tiles first
    const int hh = blockIdx.y, bb = blockIdx.z;
    const size_t base = ((size_t)(bb * NHh + hh)) * Ss * HDd;
    const int q0 = qi * AQT;
    const float Cs = 0.12751745210319466f;   // 128^-0.5 * log2(e)

    const int qrow = wid * 16 + (lane & 15);
    const int qc8 = (lane >> 4) << 3;

    // ---- prologue: Q to resident smem; KV tile 0 in flight ----
#pragma unroll
    for (int i = 0; i < 8; i++) {
        const int idx = i * 256 + tid;
        const int row = idx >> 4, ch = idx & 15;
        cp16(QH + (uint32_t)(row * PADV + ch * 8) * 2,
             Qs + base + (size_t)(q0 + row) * HDd + ch * 8);
    }
    CP_COMMIT();
    stage_kv2(KV, base, 0, Ks, Vs, tid);
    CP_COMMIT();
    CP_WAIT1();          // Q ready
    __syncthreads();

    uint32_t qfh[8][4];
#pragma unroll
    for (int kk = 0; kk < 8; kk++)
        ldm_x4(qfh[kk][0], qfh[kk][1], qfh[kk][2], qfh[kk][3],
               QH + (uint32_t)(qrow * PADV + kk * 16 + qc8) * 2);

    float O[16][4];
#pragma unroll
    for (int i = 0; i < 16; i++)
#pragma unroll
        for (int j = 0; j < 4; j++) O[i][j] = 0.f;
    float m0 = -1e30f, m1 = -1e30f, l0 = 0.f, l1 = 0.f;

    const int nkt = qi + 1;
    for (int kt = 0; kt < nkt; kt++) {
        CP_WAIT0();          // KV(kt) resident
        __syncthreads();     // all warps done with KV(kt-1); visibility of KV(kt)
        if (kt + 1 < nkt) {
            stage_kv2(KV + (uint32_t)(((kt + 1) & 1) * KV_STAGE_B), base,
                      (kt + 1) * AKT, Ks, Vs, tid);
            CP_COMMIT();
        }
        const uint32_t cur = KV + (uint32_t)((kt & 1) * KV_STAGE_B);
        const uint32_t KsS = cur, VsS = cur + KV_TILE_B;

        // ---- scores: 16 n-frags over 128 keys, single-MMA ----
        float c[16][4];
#pragma unroll
        for (int i = 0; i < 16; i++)
#pragma unroll
            for (int j = 0; j < 4; j++) c[i][j] = 0.f;

#pragma unroll
        for (int kk = 0; kk < 8; kk++) {
            const uint32_t kc = (uint32_t)(kk * 16 + ((lane >> 3) & 1) * 8) * 2;
#pragma unroll
            for (int nfp = 0; nfp < 8; nfp++) {
                const uint32_t nrow =
                    (uint32_t)(nfp * 16 + ((lane >> 4) << 3) + (lane & 7));
                uint32_t h0, h1, h2, h3;
                ldm_x4(h0, h1, h2, h3, KsS + nrow * (PADV * 2) + kc);
                uint32_t bA[2] = {h0, h1}, bB[2] = {h2, h3};
                mma_f16(c[2 * nfp],     qfh[kk], bA);
                mma_f16(c[2 * nfp + 1], qfh[kk], bB);
            }
        }

        // ---- causal mask (only the diagonal tile) ----
        if (kt == nkt - 1) {
            const int row0 = q0 + wid * 16 + (lane >> 2);
            const int col0 = kt * AKT + (lane & 3) * 2;
#pragma unroll
            for (int nf = 0; nf < 16; nf++) {
                const int cb = col0 + nf * 8;
                if (cb     > row0)     c[nf][0] = -1e30f;
                if (cb + 1 > row0)     c[nf][1] = -1e30f;
                if (cb     > row0 + 8) c[nf][2] = -1e30f;
                if (cb + 1 > row0 + 8) c[nf][3] = -1e30f;
            }
        }

        // ---- online softmax ----
        float rm0 = -1e30f, rm1 = -1e30f;
#pragma unroll
        for (int nf = 0; nf < 16; nf++) {
            rm0 = fmaxf(rm0, fmaxf(c[nf][0], c[nf][1]));
            rm1 = fmaxf(rm1, fmaxf(c[nf][2], c[nf][3]));
        }
        rm0 = fmaxf(rm0, __shfl_xor_sync(0xffffffffu, rm0, 1));
        rm0 = fmaxf(rm0, __shfl_xor_sync(0xffffffffu, rm0, 2));
        rm1 = fmaxf(rm1, __shfl_xor_sync(0xffffffffu, rm1, 1));
        rm1 = fmaxf(rm1, __shfl_xor_sync(0xffffffffu, rm1, 2));
        const float mn0 = fmaxf(m0, rm0), mn1 = fmaxf(m1, rm1);
        const float a0 = exp2p((m0 - mn0) * Cs);
        const float a1 = exp2p((m1 - mn1) * Cs);
        m0 = mn0; m1 = mn1;

        float rs0 = 0.f, rs1 = 0.f;
#pragma unroll
        for (int nf = 0; nf < 16; nf++) {
            c[nf][0] = exp2p((c[nf][0] - mn0) * Cs);
            c[nf][1] = exp2p((c[nf][1] - mn0) * Cs);
            c[nf][2] = exp2p((c[nf][2] - mn1) * Cs);
            c[nf][3] = exp2p((c[nf][3] - mn1) * Cs);
            rs0 += c[nf][0] + c[nf][1];
            rs1 += c[nf][2] + c[nf][3];
        }
        rs0 += __shfl_xor_sync(0xffffffffu, rs0, 1);
        rs0 += __shfl_xor_sync(0xffffffffu, rs0, 2);
        rs1 += __shfl_xor_sync(0xffffffffu, rs1, 1);
        rs1 += __shfl_xor_sync(0xffffffffu, rs1, 2);
        l0 = l0 * a0 + rs0;
        l1 = l1 * a1 + rs1;

#pragma unroll
        for (int i = 0; i < 16; i++) {
            O[i][0] *= a0; O[i][1] *= a0; O[i][2] *= a1; O[i][3] *= a1;
        }

        // ---- O += P @ V (P packed on the fly per 16-key group) ----
#pragma unroll
        for (int k2 = 0; k2 < 8; k2++) {
            uint32_t pah[4];
#pragma unroll
            for (int q = 0; q < 4; q++) {
                const int nf = 2 * k2 + (q >> 1);
                const int e  = (q & 1) * 2;
                pah[q] = packh(c[nf][e], c[nf][e + 1]);
            }
            const uint32_t vr =
                (uint32_t)(k2 * 16 + (lane & 7) + ((lane >> 3) & 1) * 8);
#pragma unroll
            for (int nfp = 0; nfp < 8; nfp++) {
                const uint32_t vc = (uint32_t)(nfp * 16 + ((lane >> 4) << 3));
                uint32_t h0, h1, h2, h3;
                ldm_x4t(h0, h1, h2, h3, VsS + (vr * PADV + vc) * 2);
                uint32_t bA[2] = {h0, h1}, bB[2] = {h2, h3};
                mma_f16(O[2 * nfp],     pah, bA);
                mma_f16(O[2 * nfp + 1], pah, bB);
            }
        }
    }

    // ---- epilogue: normalize, write AO single fp16 [B,S,H] ----
    const float inv0 = 1.f / l0, inv1 = 1.f / l1;
    const int srow0 = q0 + wid * 16 + (lane >> 2);
#pragma unroll
    for (int nf = 0; nf < 16; nf++) {
        const int col = hh * HDd + nf * 8 + (lane & 3) * 2;
        const size_t o0 = ((size_t)(bb * Ss) + srow0) * Hh + col;
        const size_t o1 = o0 + (size_t)8 * Hh;
        *(uint32_t*)&AOh[o0] = packh(O[nf][0] * inv0, O[nf][1] * inv0);
        *(uint32_t*)&AOh[o1] = packh(O[nf][2] * inv1, O[nf][3] * inv1);
    }
}

// ---------------------------------------------------------------------------
extern "C" void kernel_launch(void* const* d_in, const int* in_sizes, int n_in,
                              void* d_out, int out_size)
{
    (void)in_sizes; (void)n_in; (void)out_size;
    const float* x  = (const float*)d_in[0];
    const float* wq = (const float*)d_in[2];
    const float* bq = (const float*)d_in[3];
    const float* wk = (const float*)d_in[4];
    const float* bk = (const float*)d_in[5];
    const float* wv = (const float*)d_in[6];
    const float* bv = (const float*)d_in[7];
    const float* wo = (const float*)d_in[8];
    const float* bo = (const float*)d_in[9];
    float* out = (float*)d_out;

    __half *xs, *qs, *ks, *vs, *aoh, *wt;
    cudaGetSymbolAddress((void**)&xs,  g_Xs);
    cudaGetSymbolAddress((void**)&qs,  g_Qs);
    cudaGetSymbolAddress((void**)&ks,  g_Ks);
    cudaGetSymbolAddress((void**)&vs,  g_Vs);
    cudaGetSymbolAddress((void**)&aoh, g_AOh);
    cudaGetSymbolAddress((void**)&wt,  g_Wt);
    const size_t WSZ = (size_t)Hh * Hh;

    static bool attr_set = false;
    if (!attr_set) {
        cudaFuncSetAttribute(qkv_mma,
                             cudaFuncAttributeMaxDynamicSharedMemorySize, GEMM_SMEM);
        cudaFuncSetAttribute(proj_mma,
                             cudaFuncAttributeMaxDynamicSharedMemorySize, GEMM_SMEM);
        cudaFuncSetAttribute(attn_mma,
                             cudaFuncAttributeMaxDynamicSharedMemorySize, ATT2_SMEM);
        attr_set = true;
    }

    const int N2 = Mm * Hh / 2;
    convert_half<<<(N2 + 255) / 256, 256>>>(
        (const float2*)x, (__half2*)xs, N2);

    transpose_convert4<<<dim3(Hh / 32, Hh / 32, 4), dim3(32, 8)>>>(
        wq, wk, wv, wo, wt);

    // Q, K, V in one uniform launch (z selects weight/bias/output)
    qkv_mma<<<dim3(Hh / 128, Mm / 128, 3), 256, GEMM_SMEM>>>(
        xs, wt, bq, bk, bv, qs, ks, vs);

    attn_mma<<<dim3(Ss / AQT, NHh, Bb), 256, ATT2_SMEM>>>(qs, ks, vs, aoh);

    proj_mma<<<dim3(Hh / 128, Mm / 128), 256, GEMM_SMEM>>>(
        aoh, wt + 3 * WSZ, bo, out);
}

// round 12
// speedup vs baseline: 1.3417x; 1.0022x over previous
#include <cuda_runtime.h>
#include <cuda_fp16.h>
#include <cstdint>

// Problem constants
#define Bb   2
#define Ss   2048
#define Hh   2048
#define NHh  16
#define HDd  128
#define Mm   4096   // B*S

// ---------------------------------------------------------------------------
// Scratch (device globals; no allocation allowed)
// ---------------------------------------------------------------------------
__device__ __half g_Xs[(size_t)Mm * Hh];
__device__ __half g_Qs[(size_t)Mm * Hh];
__device__ __half g_Ks[(size_t)Mm * Hh];
__device__ __half g_Vs[(size_t)Mm * Hh];
__device__ __half g_AOh[(size_t)Mm * Hh];
__device__ __half g_Wt[4][(size_t)Hh * Hh];

// ---------------------------------------------------------------------------
// PTX helpers (sm_80-level only: legal in compute_103 PTX)
// ---------------------------------------------------------------------------
__device__ __forceinline__ uint32_t smem_to_u32(const void* p) {
    uint32_t a;
    asm("{ .reg .u64 t; cvta.to.shared.u64 t, %1; cvt.u32.u64 %0, t; }"
        : "=r"(a) : "l"(p));
    return a;
}
__device__ __forceinline__ void cp16(uint32_t s, const void* g) {
    asm volatile("cp.async.cg.shared.global [%0], [%1], 16;" :: "r"(s), "l"(g));
}
#define CP_COMMIT() asm volatile("cp.async.commit_group;" ::: "memory")
#define CP_WAIT0()  asm volatile("cp.async.wait_group 0;" ::: "memory")
#define CP_WAIT1()  asm volatile("cp.async.wait_group 1;" ::: "memory")

__device__ __forceinline__ void ldm_x4(uint32_t& r0, uint32_t& r1, uint32_t& r2,
                                       uint32_t& r3, uint32_t addr) {
    asm volatile("ldmatrix.sync.aligned.m8n8.x4.shared.b16 {%0,%1,%2,%3}, [%4];"
                 : "=r"(r0), "=r"(r1), "=r"(r2), "=r"(r3) : "r"(addr));
}
__device__ __forceinline__ void ldm_x4t(uint32_t& r0, uint32_t& r1, uint32_t& r2,
                                        uint32_t& r3, uint32_t addr) {
    asm volatile("ldmatrix.sync.aligned.m8n8.x4.trans.shared.b16 {%0,%1,%2,%3}, [%4];"
                 : "=r"(r0), "=r"(r1), "=r"(r2), "=r"(r3) : "r"(addr));
}
__device__ __forceinline__ void mma_f16(float* c, const uint32_t* a, const uint32_t* b) {
    asm volatile("mma.sync.aligned.m16n8k16.row.col.f32.f16.f16.f32 "
                 "{%0,%1,%2,%3}, {%4,%5,%6,%7}, {%8,%9}, {%0,%1,%2,%3};"
                 : "+f"(c[0]), "+f"(c[1]), "+f"(c[2]), "+f"(c[3])
                 : "r"(a[0]), "r"(a[1]), "r"(a[2]), "r"(a[3]), "r"(b[0]), "r"(b[1]));
}

// Fast exp2 on the FMA pipe (deg-5 poly, f in [-0.5,0.5]); rel err ~2.4e-6.
__device__ __forceinline__ float exp2p(float t) {
    t = fmaxf(t, -120.f);
    float fn = t + 12582912.f;
    int   n  = __float_as_int(fn) - 0x4B400000;
    float f  = t - (fn - 12582912.f);
    float p  = 1.3333558146428443e-3f;
    p = fmaf(p, f, 9.6181291076284772e-3f);
    p = fmaf(p, f, 5.5504108664821580e-2f);
    p = fmaf(p, f, 2.4022650695910071e-1f);
    p = fmaf(p, f, 6.9314718055994531e-1f);
    p = fmaf(p, f, 1.0f);
    return p * __int_as_float((n + 127) << 23);
}

__device__ __forceinline__ uint32_t packh(float x, float y) {
    __half2 t = __floats2half2_rn(x, y);
    return *reinterpret_cast<uint32_t*>(&t);
}

// ---------------------------------------------------------------------------
// Conversions
// ---------------------------------------------------------------------------
__global__ void convert_half(const float2* __restrict__ X,
                             __half2* __restrict__ Xs, int n2)
{
    int i = blockIdx.x * blockDim.x + threadIdx.x;
    if (i >= n2) return;
    float2 v = X[i];
    Xs[i] = __floats2half2_rn(v.x, v.y);
}

// Fused transpose + convert for all 4 weights (z selects the matrix)
__global__ void transpose_convert4(const float* __restrict__ w0,
                                   const float* __restrict__ w1,
                                   const float* __restrict__ w2,
                                   const float* __restrict__ w3,
                                   __half* __restrict__ T)
{
    __shared__ float t[32][33];
    const float* W = (blockIdx.z == 0) ? w0 : (blockIdx.z == 1) ? w1
                   : (blockIdx.z == 2) ? w2 : w3;
    __half* Td = T + (size_t)blockIdx.z * Hh * Hh;
    const int n0 = blockIdx.x * 32, k0 = blockIdx.y * 32;
    const int tx = threadIdx.x, ty = threadIdx.y;   // (32, 8)
#pragma unroll
    for (int i = 0; i < 4; i++)
        t[ty + 8 * i][tx] = W[(size_t)(k0 + ty + 8 * i) * Hh + n0 + tx];
    __syncthreads();
#pragma unroll
    for (int i = 0; i < 4; i++)
        Td[(size_t)(n0 + ty + 8 * i) * Hh + k0 + tx] =
            __float2half_rn(t[tx][ty + 8 * i]);
}

// ---------------------------------------------------------------------------
// GEMM geometry: BK=64, 3-stage pipeline (prefetch distance 2), 2 CTAs/SM.
// Stage = [A tile][B tile], each 128x64 halfs padded to 72/row.
// 64 MMAs between barriers (vs 32 at BK=32); one __syncthreads per kt.
// ---------------------------------------------------------------------------
#define BKg   64
#define PADR  72
#define TILE_HALFS (128 * PADR)               // 9216
#define TILE_B ((uint32_t)(TILE_HALFS * 2))   // 18432 bytes
#define STAGE_B (2u * TILE_B)                 // 36864 bytes
#define GEMM_SMEM (3 * 2 * (int)TILE_B)       // 110592 bytes

__device__ __forceinline__ void stage_load(uint32_t sb,
    const __half* __restrict__ As, const __half* __restrict__ Bs,
    int bm, int bn, int k0, int tid)
{
    const int r = tid >> 1;
    const int c = (tid & 1) * 4;
#pragma unroll
    for (int cc = 0; cc < 4; cc++) {
        const uint32_t so = (uint32_t)(r * PADR + (c + cc) * 8) * 2;
        const size_t go = (size_t)k0 + (c + cc) * 8;
        cp16(sb + so,          As + (size_t)(bm + r) * Hh + go);
        cp16(sb + TILE_B + so, Bs + (size_t)(bn + r) * Hh + go);
    }
}

// Shared inner compute: one BK=64 stage (4 k-slices of 16)
__device__ __forceinline__ void gemm_stage_compute(
    uint32_t sb, float acc[4][4][4], int wm, int wn, int lane)
{
    const int arow = lane & 15;
    const int acol8 = (lane >> 4) << 3;
    const int bq8 = ((lane >> 3) & 1) << 3;
    const int brow8 = ((lane >> 4) << 3) + (lane & 7);
#pragma unroll
    for (int ks = 0; ks < 4; ks++) {
        const int k0 = ks * 16;
        uint32_t bF[4][2];
#pragma unroll
        for (int pair = 0; pair < 2; pair++) {
            const uint32_t nrow = (uint32_t)(wn + pair * 16 + brow8);
            const uint32_t off = (nrow * PADR + k0 + bq8) * 2;
            ldm_x4(bF[2 * pair][0], bF[2 * pair][1],
                   bF[2 * pair + 1][0], bF[2 * pair + 1][1],
                   sb + TILE_B + off);
        }
#pragma unroll
        for (int mi = 0; mi < 4; mi++) {
            const uint32_t off =
                (uint32_t)((wm + mi * 16 + arow) * PADR + k0 + acol8) * 2;
            uint32_t aH[4];
            ldm_x4(aH[0], aH[1], aH[2], aH[3], sb + off);
#pragma unroll
            for (int ni = 0; ni < 4; ni++)
                mma_f16(acc[mi][ni], aH, bF[ni]);
        }
    }
}

// ---------------------------------------------------------------------------
// Merged QKV GEMM: uniform single-MMA; z selects weight/bias/output.
// ---------------------------------------------------------------------------
__global__ __launch_bounds__(256, 2)
void qkv_mma(const __half* __restrict__ Xs, const __half* __restrict__ Wt,
             const float* __restrict__ bq, const float* __restrict__ bk,
             const float* __restrict__ bv,
             __half* __restrict__ Qs, __half* __restrict__ Ks,
             __half* __restrict__ Vs)
{
    extern __shared__ __half smem[];
    const uint32_t sbase = smem_to_u32(smem);
    const int tid = threadIdx.x;
    const int wid = tid >> 5, lane = tid & 31;
    const int z = blockIdx.z;
    const __half* Bs = Wt + (size_t)z * Hh * Hh;
    const float* bias = (z == 0) ? bq : (z == 1) ? bk : bv;
    __half* Co = (z == 0) ? Qs : (z == 1) ? Ks : Vs;
    const int bn = blockIdx.x * 128, bm = blockIdx.y * 128;
    const int wm = (wid >> 2) * 64;
    const int wn = (wid & 3) * 32;

    float acc[4][4][4];
#pragma unroll
    for (int i = 0; i < 4; i++)
#pragma unroll
        for (int j = 0; j < 4; j++)
#pragma unroll
            for (int q = 0; q < 4; q++) acc[i][j][q] = 0.f;

    const int NIT = Hh / BKg;   // 32
    stage_load(sbase, Xs, Bs, bm, bn, 0, tid);
    CP_COMMIT();
    stage_load(sbase + STAGE_B, Xs, Bs, bm, bn, BKg, tid);
    CP_COMMIT();
    CP_WAIT1();
    __syncthreads();

    for (int kt = 0; kt < NIT; kt++) {
        const uint32_t sb = sbase + (uint32_t)(kt % 3) * STAGE_B;
        if (kt + 2 < NIT) {
            stage_load(sbase + (uint32_t)((kt + 2) % 3) * STAGE_B,
                       Xs, Bs, bm, bn, (kt + 2) * BKg, tid);
            CP_COMMIT();
        }

        gemm_stage_compute(sb, acc, wm, wn, lane);

        if (kt + 1 < NIT) {
            if (kt + 2 < NIT) { CP_WAIT1(); } else { CP_WAIT0(); }
        }
        __syncthreads();
    }

    const int fr = lane >> 2;
    const int fc = (lane & 3) * 2;
#pragma unroll
    for (int mi = 0; mi < 4; mi++) {
#pragma unroll
        for (int ni = 0; ni < 4; ni++) {
            const int n0 = bn + wn + ni * 8 + fc;
            const float b0 = bias[n0], b1 = bias[n0 + 1];
#pragma unroll
            for (int half = 0; half < 2; half++) {
                const int m = bm + wm + mi * 16 + fr + half * 8;
                float v0 = acc[mi][ni][half * 2 + 0] + b0;
                float v1 = acc[mi][ni][half * 2 + 1] + b1;
                const int bb = m >> 11;
                const int ss = m & (Ss - 1);
                const int hh = n0 >> 7;
                const int dd = n0 & (HDd - 1);
                const size_t idx =
                    (((size_t)(bb * NHh + hh) * Ss) + ss) * HDd + dd;
                *(__half2*)&Co[idx] = __floats2half2_rn(v0, v1);
            }
        }
    }
}

// ---------------------------------------------------------------------------
// Output projection GEMM: C[M,N] = A @ B^T + bias, fp32 row-major out.
// ---------------------------------------------------------------------------
__global__ __launch_bounds__(256, 2)
void proj_mma(const __half* __restrict__ Ah, const __half* __restrict__ Bw,
              const float* __restrict__ bias, float* __restrict__ Cf)
{
    extern __shared__ __half smem[];
    const uint32_t sbase = smem_to_u32(smem);
    const int tid = threadIdx.x;
    const int wid = tid >> 5, lane = tid & 31;
    const int bn = blockIdx.x * 128, bm = blockIdx.y * 128;
    const int wm = (wid >> 2) * 64;
    const int wn = (wid & 3) * 32;

    float acc[4][4][4];
#pragma unroll
    for (int i = 0; i < 4; i++)
#pragma unroll
        for (int j = 0; j < 4; j++)
#pragma unroll
            for (int q = 0; q < 4; q++) acc[i][j][q] = 0.f;

    const int NIT = Hh / BKg;   // 32
    stage_load(sbase, Ah, Bw, bm, bn, 0, tid);
    CP_COMMIT();
    stage_load(sbase + STAGE_B, Ah, Bw, bm, bn, BKg, tid);
    CP_COMMIT();
    CP_WAIT1();
    __syncthreads();

    for (int kt = 0; kt < NIT; kt++) {
        const uint32_t sb = sbase + (uint32_t)(kt % 3) * STAGE_B;
        if (kt + 2 < NIT) {
            stage_load(sbase + (uint32_t)((kt + 2) % 3) * STAGE_B,
                       Ah, Bw, bm, bn, (kt + 2) * BKg, tid);
            CP_COMMIT();
        }

        gemm_stage_compute(sb, acc, wm, wn, lane);

        if (kt + 1 < NIT) {
            if (kt + 2 < NIT) { CP_WAIT1(); } else { CP_WAIT0(); }
        }
        __syncthreads();
    }

    const int fr = lane >> 2;
    const int fc = (lane & 3) * 2;
#pragma unroll
    for (int mi = 0; mi < 4; mi++) {
#pragma unroll
        for (int ni = 0; ni < 4; ni++) {
            const int n0 = bn + wn + ni * 8 + fc;
            const float b0 = bias[n0], b1 = bias[n0 + 1];
#pragma unroll
            for (int half = 0; half < 2; half++) {
                const int m = bm + wm + mi * 16 + fr + half * 8;
                float2 w;
                w.x = acc[mi][ni][half * 2 + 0] + b0;
                w.y = acc[mi][ni][half * 2 + 1] + b1;
                *(float2*)&Cf[(size_t)m * Hh + n0] = w;
            }
        }
    }
}

// ---------------------------------------------------------------------------
// HMMA fp16 flash attention: single-fp16 Q/K/V, AKT=128, single sync/kt.
// CTA: 128 q rows, 8 warps x 16 rows. KV double-buffered cp.async. (R11 proven)
// ---------------------------------------------------------------------------
#define AQT 128
#define AKT 128
#define PADV 136
#define Q_TILE_B   (AQT * PADV * 2)        // 34816 bytes
#define KV_TILE_B  (AKT * PADV * 2)        // 34816 bytes
#define KV_STAGE_B (2 * KV_TILE_B)         // K, V = 69632 bytes
#define ATT2_SMEM  (Q_TILE_B + 2 * KV_STAGE_B)   // 174080 bytes

__device__ __forceinline__ void stage_kv2(uint32_t dst, size_t base, int kn0,
    const __half* __restrict__ Ks, const __half* __restrict__ Vs, int tid)
{
#pragma unroll
    for (int i = 0; i < 8; i++) {
        const int idx = i * 256 + tid;
        const int row = idx >> 4, ch = idx & 15;
        const uint32_t so = (uint32_t)(row * PADV + ch * 8) * 2;
        const size_t go = base + (size_t)(kn0 + row) * HDd + ch * 8;
        cp16(dst +             so, Ks + go);
        cp16(dst + KV_TILE_B + so, Vs + go);
    }
}

__global__ __launch_bounds__(256, 1)
void attn_mma(const __half* __restrict__ Qs, const __half* __restrict__ Ks,
              const __half* __restrict__ Vs, __half* __restrict__ AOh)
{
    extern __shared__ __half asmem[];
    const uint32_t sb = smem_to_u32(asmem);
    const uint32_t QH = sb, KV = sb + Q_TILE_B;
    const int tid = threadIdx.x, wid = tid >> 5, lane = tid & 31;
    const int qi = (int)gridDim.x - 1 - (int)blockIdx.x;   // big tiles first
    const int hh = blockIdx.y, bb = blockIdx.z;
    const size_t base = ((size_t)(bb * NHh + hh)) * Ss * HDd;
    const int q0 = qi * AQT;
    const float Cs = 0.12751745210319466f;   // 128^-0.5 * log2(e)

    const int qrow = wid * 16 + (lane & 15);
    const int qc8 = (lane >> 4) << 3;

    // ---- prologue: Q to resident smem; KV tile 0 in flight ----
#pragma unroll
    for (int i = 0; i < 8; i++) {
        const int idx = i * 256 + tid;
        const int row = idx >> 4, ch = idx & 15;
        cp16(QH + (uint32_t)(row * PADV + ch * 8) * 2,
             Qs + base + (size_t)(q0 + row) * HDd + ch * 8);
    }
    CP_COMMIT();
    stage_kv2(KV, base, 0, Ks, Vs, tid);
    CP_COMMIT();
    CP_WAIT1();          // Q ready
    __syncthreads();

    uint32_t qfh[8][4];
#pragma unroll
    for (int kk = 0; kk < 8; kk++)
        ldm_x4(qfh[kk][0], qfh[kk][1], qfh[kk][2], qfh[kk][3],
               QH + (uint32_t)(qrow * PADV + kk * 16 + qc8) * 2);

    float O[16][4];
#pragma unroll
    for (int i = 0; i < 16; i++)
#pragma unroll
        for (int j = 0; j < 4; j++) O[i][j] = 0.f;
    float m0 = -1e30f, m1 = -1e30f, l0 = 0.f, l1 = 0.f;

    const int nkt = qi + 1;
    for (int kt = 0; kt < nkt; kt++) {
        CP_WAIT0();          // KV(kt) resident
        __syncthreads();     // all warps done with KV(kt-1); visibility of KV(kt)
        if (kt + 1 < nkt) {
            stage_kv2(KV + (uint32_t)(((kt + 1) & 1) * KV_STAGE_B), base,
                      (kt + 1) * AKT, Ks, Vs, tid);
            CP_COMMIT();
        }
        const uint32_t cur = KV + (uint32_t)((kt & 1) * KV_STAGE_B);
        const uint32_t KsS = cur, VsS = cur + KV_TILE_B;

        // ---- scores: 16 n-frags over 128 keys, single-MMA ----
        float c[16][4];
#pragma unroll
        for (int i = 0; i < 16; i++)
#pragma unroll
            for (int j = 0; j < 4; j++) c[i][j] = 0.f;

#pragma unroll
        for (int kk = 0; kk < 8; kk++) {
            const uint32_t kc = (uint32_t)(kk * 16 + ((lane >> 3) & 1) * 8) * 2;
#pragma unroll
            for (int nfp = 0; nfp < 8; nfp++) {
                const uint32_t nrow =
                    (uint32_t)(nfp * 16 + ((lane >> 4) << 3) + (lane & 7));
                uint32_t h0, h1, h2, h3;
                ldm_x4(h0, h1, h2, h3, KsS + nrow * (PADV * 2) + kc);
                uint32_t bA[2] = {h0, h1}, bB[2] = {h2, h3};
                mma_f16(c[2 * nfp],     qfh[kk], bA);
                mma_f16(c[2 * nfp + 1], qfh[kk], bB);
            }
        }

        // ---- causal mask (only the diagonal tile) ----
        if (kt == nkt - 1) {
            const int row0 = q0 + wid * 16 + (lane >> 2);
            const int col0 = kt * AKT + (lane & 3) * 2;
#pragma unroll
            for (int nf = 0; nf < 16; nf++) {
                const int cb = col0 + nf * 8;
                if (cb     > row0)     c[nf][0] = -1e30f;
                if (cb + 1 > row0)     c[nf][1] = -1e30f;
                if (cb     > row0 + 8) c[nf][2] = -1e30f;
                if (cb + 1 > row0 + 8) c[nf][3] = -1e30f;
            }
        }

        // ---- online softmax ----
        float rm0 = -1e30f, rm1 = -1e30f;
#pragma unroll
        for (int nf = 0; nf < 16; nf++) {
            rm0 = fmaxf(rm0, fmaxf(c[nf][0], c[nf][1]));
            rm1 = fmaxf(rm1, fmaxf(c[nf][2], c[nf][3]));
        }
        rm0 = fmaxf(rm0, __shfl_xor_sync(0xffffffffu, rm0, 1));
        rm0 = fmaxf(rm0, __shfl_xor_sync(0xffffffffu, rm0, 2));
        rm1 = fmaxf(rm1, __shfl_xor_sync(0xffffffffu, rm1, 1));
        rm1 = fmaxf(rm1, __shfl_xor_sync(0xffffffffu, rm1, 2));
        const float mn0 = fmaxf(m0, rm0), mn1 = fmaxf(m1, rm1);
        const float a0 = exp2p((m0 - mn0) * Cs);
        const float a1 = exp2p((m1 - mn1) * Cs);
        m0 = mn0; m1 = mn1;

        float rs0 = 0.f, rs1 = 0.f;
#pragma unroll
        for (int nf = 0; nf < 16; nf++) {
            c[nf][0] = exp2p((c[nf][0] - mn0) * Cs);
            c[nf][1] = exp2p((c[nf][1] - mn0) * Cs);
            c[nf][2] = exp2p((c[nf][2] - mn1) * Cs);
            c[nf][3] = exp2p((c[nf][3] - mn1) * Cs);
            rs0 += c[nf][0] + c[nf][1];
            rs1 += c[nf][2] + c[nf][3];
        }
        rs0 += __shfl_xor_sync(0xffffffffu, rs0, 1);
        rs0 += __shfl_xor_sync(0xffffffffu, rs0, 2);
        rs1 += __shfl_xor_sync(0xffffffffu, rs1, 1);
        rs1 += __shfl_xor_sync(0xffffffffu, rs1, 2);
        l0 = l0 * a0 + rs0;
        l1 = l1 * a1 + rs1;

#pragma unroll
        for (int i = 0; i < 16; i++) {
            O[i][0] *= a0; O[i][1] *= a0; O[i][2] *= a1; O[i][3] *= a1;
        }

        // ---- O += P @ V (P packed on the fly per 16-key group) ----
#pragma unroll
        for (int k2 = 0; k2 < 8; k2++) {
            uint32_t pah[4];
#pragma unroll
            for (int q = 0; q < 4; q++) {
                const int nf = 2 * k2 + (q >> 1);
                const int e  = (q & 1) * 2;
                pah[q] = packh(c[nf][e], c[nf][e + 1]);
            }
            const uint32_t vr =
                (uint32_t)(k2 * 16 + (lane & 7) + ((lane >> 3) & 1) * 8);
#pragma unroll
            for (int nfp = 0; nfp < 8; nfp++) {
                const uint32_t vc = (uint32_t)(nfp * 16 + ((lane >> 4) << 3));
                uint32_t h0, h1, h2, h3;
                ldm_x4t(h0, h1, h2, h3, VsS + (vr * PADV + vc) * 2);
                uint32_t bA[2] = {h0, h1}, bB[2] = {h2, h3};
                mma_f16(O[2 * nfp],     pah, bA);
                mma_f16(O[2 * nfp + 1], pah, bB);
            }
        }
    }

    // ---- epilogue: normalize, write AO single fp16 [B,S,H] ----
    const float inv0 = 1.f / l0, inv1 = 1.f / l1;
    const int srow0 = q0 + wid * 16 + (lane >> 2);
#pragma unroll
    for (int nf = 0; nf < 16; nf++) {
        const int col = hh * HDd + nf * 8 + (lane & 3) * 2;
        const size_t o0 = ((size_t)(bb * Ss) + srow0) * Hh + col;
        const size_t o1 = o0 + (size_t)8 * Hh;
        *(uint32_t*)&AOh[o0] = packh(O[nf][0] * inv0, O[nf][1] * inv0);
        *(uint32_t*)&AOh[o1] = packh(O[nf][2] * inv1, O[nf][3] * inv1);
    }
}

// ---------------------------------------------------------------------------
extern "C" void kernel_launch(void* const* d_in, const int* in_sizes, int n_in,
                              void* d_out, int out_size)
{
    (void)in_sizes; (void)n_in; (void)out_size;
    const float* x  = (const float*)d_in[0];
    const float* wq = (const float*)d_in[2];
    const float* bq = (const float*)d_in[3];
    const float* wk = (const float*)d_in[4];
    const float* bk = (const float*)d_in[5];
    const float* wv = (const float*)d_in[6];
    const float* bv = (const float*)d_in[7];
    const float* wo = (const float*)d_in[8];
    const float* bo = (const float*)d_in[9];
    float* out = (float*)d_out;

    __half *xs, *qs, *ks, *vs, *aoh, *wt;
    cudaGetSymbolAddress((void**)&xs,  g_Xs);
    cudaGetSymbolAddress((void**)&qs,  g_Qs);
    cudaGetSymbolAddress((void**)&ks,  g_Ks);
    cudaGetSymbolAddress((void**)&vs,  g_Vs);
    cudaGetSymbolAddress((void**)&aoh, g_AOh);
    cudaGetSymbolAddress((void**)&wt,  g_Wt);
    const size_t WSZ = (size_t)Hh * Hh;

    static bool attr_set = false;
    if (!attr_set) {
        cudaFuncSetAttribute(qkv_mma,
                             cudaFuncAttributeMaxDynamicSharedMemorySize, GEMM_SMEM);
        cudaFuncSetAttribute(proj_mma,
                             cudaFuncAttributeMaxDynamicSharedMemorySize, GEMM_SMEM);
        cudaFuncSetAttribute(attn_mma,
                             cudaFuncAttributeMaxDynamicSharedMemorySize, ATT2_SMEM);
        attr_set = true;
    }

    const int N2 = Mm * Hh / 2;
    convert_half<<<(N2 + 255) / 256, 256>>>(
        (const float2*)x, (__half2*)xs, N2);

    transpose_convert4<<<dim3(Hh / 32, Hh / 32, 4), dim3(32, 8)>>>(
        wq, wk, wv, wo, wt);

    // Q, K, V in one uniform launch (z selects weight/bias/output)
    qkv_mma<<<dim3(Hh / 128, Mm / 128, 3), 256, GEMM_SMEM>>>(
        xs, wt, bq, bk, bv, qs, ks, vs);

    attn_mma<<<dim3(Ss / AQT, NHh, Bb), 256, ATT2_SMEM>>>(qs, ks, vs, aoh);

    proj_mma<<<dim3(Hh / 128, Mm / 128), 256, GEMM_SMEM>>>(
        aoh, wt + 3 * WSZ, bo, out);
}

// round 13
// speedup vs baseline: 1.6014x; 1.1936x over previous
#include <cuda_runtime.h>
#include <cuda_fp16.h>
#include <cstdint>

// Problem constants
#define Bb   2
#define Ss   2048
#define Hh   2048
#define NHh  16
#define HDd  128
#define Mm   4096   // B*S

// ---------------------------------------------------------------------------
// Scratch (device globals; no allocation allowed)
// ---------------------------------------------------------------------------
__device__ __half g_Xs[(size_t)Mm * Hh];
__device__ __half g_Qs[(size_t)Mm * Hh];
__device__ __half g_Ks[(size_t)Mm * Hh];
__device__ __half g_Vs[(size_t)Mm * Hh];
__device__ __half g_AOh[(size_t)Mm * Hh];
__device__ __half g_Wt[4][(size_t)Hh * Hh];

// ---------------------------------------------------------------------------
// PTX helpers (sm_80-level only: legal in compute_103 PTX)
// ---------------------------------------------------------------------------
__device__ __forceinline__ uint32_t smem_to_u32(const void* p) {
    uint32_t a;
    asm("{ .reg .u64 t; cvta.to.shared.u64 t, %1; cvt.u32.u64 %0, t; }"
        : "=r"(a) : "l"(p));
    return a;
}
__device__ __forceinline__ void cp16(uint32_t s, const void* g) {
    asm volatile("cp.async.cg.shared.global [%0], [%1], 16;" :: "r"(s), "l"(g));
}
#define CP_COMMIT() asm volatile("cp.async.commit_group;" ::: "memory")
#define CP_WAIT0()  asm volatile("cp.async.wait_group 0;" ::: "memory")
#define CP_WAIT1()  asm volatile("cp.async.wait_group 1;" ::: "memory")

__device__ __forceinline__ void ldm_x4(uint32_t& r0, uint32_t& r1, uint32_t& r2,
                                       uint32_t& r3, uint32_t addr) {
    asm volatile("ldmatrix.sync.aligned.m8n8.x4.shared.b16 {%0,%1,%2,%3}, [%4];"
                 : "=r"(r0), "=r"(r1), "=r"(r2), "=r"(r3) : "r"(addr));
}
__device__ __forceinline__ void ldm_x4t(uint32_t& r0, uint32_t& r1, uint32_t& r2,
                                        uint32_t& r3, uint32_t addr) {
    asm volatile("ldmatrix.sync.aligned.m8n8.x4.trans.shared.b16 {%0,%1,%2,%3}, [%4];"
                 : "=r"(r0), "=r"(r1), "=r"(r2), "=r"(r3) : "r"(addr));
}
__device__ __forceinline__ void mma_f16(float* c, const uint32_t* a, const uint32_t* b) {
    asm volatile("mma.sync.aligned.m16n8k16.row.col.f32.f16.f16.f32 "
                 "{%0,%1,%2,%3}, {%4,%5,%6,%7}, {%8,%9}, {%0,%1,%2,%3};"
                 : "+f"(c[0]), "+f"(c[1]), "+f"(c[2]), "+f"(c[3])
                 : "r"(a[0]), "r"(a[1]), "r"(a[2]), "r"(a[3]), "r"(b[0]), "r"(b[1]));
}

// Fast exp2 on the FMA pipe (deg-5 poly, f in [-0.5,0.5]); rel err ~2.4e-6.
__device__ __forceinline__ float exp2p(float t) {
    t = fmaxf(t, -120.f);
    float fn = t + 12582912.f;
    int   n  = __float_as_int(fn) - 0x4B400000;
    float f  = t - (fn - 12582912.f);
    float p  = 1.3333558146428443e-3f;
    p = fmaf(p, f, 9.6181291076284772e-3f);
    p = fmaf(p, f, 5.5504108664821580e-2f);
    p = fmaf(p, f, 2.4022650695910071e-1f);
    p = fmaf(p, f, 6.9314718055994531e-1f);
    p = fmaf(p, f, 1.0f);
    return p * __int_as_float((n + 127) << 23);
}

__device__ __forceinline__ uint32_t packh(float x, float y) {
    __half2 t = __floats2half2_rn(x, y);
    return *reinterpret_cast<uint32_t*>(&t);
}

// ---------------------------------------------------------------------------
// Conversions
// ---------------------------------------------------------------------------
__global__ void convert_half(const float2* __restrict__ X,
                             __half2* __restrict__ Xs, int n2)
{
    int i = blockIdx.x * blockDim.x + threadIdx.x;
    if (i >= n2) return;
    float2 v = X[i];
    Xs[i] = __floats2half2_rn(v.x, v.y);
}

// Fused transpose + convert for all 4 weights (z selects the matrix)
__global__ void transpose_convert4(const float* __restrict__ w0,
                                   const float* __restrict__ w1,
                                   const float* __restrict__ w2,
                                   const float* __restrict__ w3,
                                   __half* __restrict__ T)
{
    __shared__ float t[32][33];
    const float* W = (blockIdx.z == 0) ? w0 : (blockIdx.z == 1) ? w1
                   : (blockIdx.z == 2) ? w2 : w3;
    __half* Td = T + (size_t)blockIdx.z * Hh * Hh;
    const int n0 = blockIdx.x * 32, k0 = blockIdx.y * 32;
    const int tx = threadIdx.x, ty = threadIdx.y;   // (32, 8)
#pragma unroll
    for (int i = 0; i < 4; i++)
        t[ty + 8 * i][tx] = W[(size_t)(k0 + ty + 8 * i) * Hh + n0 + tx];
    __syncthreads();
#pragma unroll
    for (int i = 0; i < 4; i++)
        Td[(size_t)(n0 + ty + 8 * i) * Hh + k0 + tx] =
            __float2half_rn(t[tx][ty + 8 * i]);
}

// ---------------------------------------------------------------------------
// GEMM geometry: CTA 128x128, 512 threads (16 warps, warp tile 32x32),
// BK=64, 3-stage pipeline, 2 CTAs/SM (32 warps/SM, occ 50%).
// acc = 32 regs/thread -> fits 64-reg budget for full-RF dual residency.
// ---------------------------------------------------------------------------
#define BKg   64
#define PADR  72
#define TILE_HALFS (128 * PADR)               // 9216
#define TILE_B ((uint32_t)(TILE_HALFS * 2))   // 18432 bytes
#define STAGE_B (2u * TILE_B)                 // 36864 bytes
#define GEMM_SMEM (3 * 2 * (int)TILE_B)       // 110592 bytes

// 512 threads: r = tid>>2 (row), chunk col = (tid&3)*2 + cc; 2 cp16 per tile.
__device__ __forceinline__ void stage_load(uint32_t sb,
    const __half* __restrict__ As, const __half* __restrict__ Bs,
    int bm, int bn, int k0, int tid)
{
    const int r = tid >> 2;
    const int c = (tid & 3) * 2;
#pragma unroll
    for (int cc = 0; cc < 2; cc++) {
        const uint32_t so = (uint32_t)(r * PADR + (c + cc) * 8) * 2;
        const size_t go = (size_t)k0 + (c + cc) * 8;
        cp16(sb + so,          As + (size_t)(bm + r) * Hh + go);
        cp16(sb + TILE_B + so, Bs + (size_t)(bn + r) * Hh + go);
    }
}

// One BK=64 stage: 4 k-slices; warp tile 32x32 (mi 0..1, ni 0..3).
__device__ __forceinline__ void gemm_stage_compute(
    uint32_t sb, float acc[2][4][4], int wm, int wn, int lane)
{
    const int arow = lane & 15;
    const int acol8 = (lane >> 4) << 3;
    const int bq8 = ((lane >> 3) & 1) << 3;
    const int brow8 = ((lane >> 4) << 3) + (lane & 7);
#pragma unroll
    for (int ks = 0; ks < 4; ks++) {
        const int k0 = ks * 16;
        uint32_t bF[4][2];
#pragma unroll
        for (int pair = 0; pair < 2; pair++) {
            const uint32_t nrow = (uint32_t)(wn + pair * 16 + brow8);
            const uint32_t off = (nrow * PADR + k0 + bq8) * 2;
            ldm_x4(bF[2 * pair][0], bF[2 * pair][1],
                   bF[2 * pair + 1][0], bF[2 * pair + 1][1],
                   sb + TILE_B + off);
        }
#pragma unroll
        for (int mi = 0; mi < 2; mi++) {
            const uint32_t off =
                (uint32_t)((wm + mi * 16 + arow) * PADR + k0 + acol8) * 2;
            uint32_t aH[4];
            ldm_x4(aH[0], aH[1], aH[2], aH[3], sb + off);
#pragma unroll
            for (int ni = 0; ni < 4; ni++)
                mma_f16(acc[mi][ni], aH, bF[ni]);
        }
    }
}

// ---------------------------------------------------------------------------
// Merged QKV GEMM: uniform single-MMA; z selects weight/bias/output.
// ---------------------------------------------------------------------------
__global__ __launch_bounds__(512, 2)
void qkv_mma(const __half* __restrict__ Xs, const __half* __restrict__ Wt,
             const float* __restrict__ bq, const float* __restrict__ bk,
             const float* __restrict__ bv,
             __half* __restrict__ Qs, __half* __restrict__ Ks,
             __half* __restrict__ Vs)
{
    extern __shared__ __half smem[];
    const uint32_t sbase = smem_to_u32(smem);
    const int tid = threadIdx.x;
    const int wid = tid >> 5, lane = tid & 31;
    const int z = blockIdx.z;
    const __half* Bs = Wt + (size_t)z * Hh * Hh;
    const float* bias = (z == 0) ? bq : (z == 1) ? bk : bv;
    __half* Co = (z == 0) ? Qs : (z == 1) ? Ks : Vs;
    const int bn = blockIdx.x * 128, bm = blockIdx.y * 128;
    const int wm = (wid & 3) * 32;     // warp row (4 rows of 32)
    const int wn = (wid >> 2) * 32;    // warp col (4 cols of 32)

    float acc[2][4][4];
#pragma unroll
    for (int i = 0; i < 2; i++)
#pragma unroll
        for (int j = 0; j < 4; j++)
#pragma unroll
            for (int q = 0; q < 4; q++) acc[i][j][q] = 0.f;

    const int NIT = Hh / BKg;   // 32
    stage_load(sbase, Xs, Bs, bm, bn, 0, tid);
    CP_COMMIT();
    stage_load(sbase + STAGE_B, Xs, Bs, bm, bn, BKg, tid);
    CP_COMMIT();
    CP_WAIT1();
    __syncthreads();

    for (int kt = 0; kt < NIT; kt++) {
        const uint32_t sb = sbase + (uint32_t)(kt % 3) * STAGE_B;
        if (kt + 2 < NIT) {
            stage_load(sbase + (uint32_t)((kt + 2) % 3) * STAGE_B,
                       Xs, Bs, bm, bn, (kt + 2) * BKg, tid);
            CP_COMMIT();
        }

        gemm_stage_compute(sb, acc, wm, wn, lane);

        if (kt + 1 < NIT) {
            if (kt + 2 < NIT) { CP_WAIT1(); } else { CP_WAIT0(); }
        }
        __syncthreads();
    }

    const int fr = lane >> 2;
    const int fc = (lane & 3) * 2;
#pragma unroll
    for (int mi = 0; mi < 2; mi++) {
#pragma unroll
        for (int ni = 0; ni < 4; ni++) {
            const int n0 = bn + wn + ni * 8 + fc;
            const float b0 = bias[n0], b1 = bias[n0 + 1];
#pragma unroll
            for (int half = 0; half < 2; half++) {
                const int m = bm + wm + mi * 16 + fr + half * 8;
                float v0 = acc[mi][ni][half * 2 + 0] + b0;
                float v1 = acc[mi][ni][half * 2 + 1] + b1;
                const int bb = m >> 11;
                const int ss = m & (Ss - 1);
                const int hh = n0 >> 7;
                const int dd = n0 & (HDd - 1);
                const size_t idx =
                    (((size_t)(bb * NHh + hh) * Ss) + ss) * HDd + dd;
                *(__half2*)&Co[idx] = __floats2half2_rn(v0, v1);
            }
        }
    }
}

// ---------------------------------------------------------------------------
// Output projection GEMM: C[M,N] = A @ B^T + bias, fp32 row-major out.
// ---------------------------------------------------------------------------
__global__ __launch_bounds__(512, 2)
void proj_mma(const __half* __restrict__ Ah, const __half* __restrict__ Bw,
              const float* __restrict__ bias, float* __restrict__ Cf)
{
    extern __shared__ __half smem[];
    const uint32_t sbase = smem_to_u32(smem);
    const int tid = threadIdx.x;
    const int wid = tid >> 5, lane = tid & 31;
    const int bn = blockIdx.x * 128, bm = blockIdx.y * 128;
    const int wm = (wid & 3) * 32;
    const int wn = (wid >> 2) * 32;

    float acc[2][4][4];
#pragma unroll
    for (int i = 0; i < 2; i++)
#pragma unroll
        for (int j = 0; j < 4; j++)
#pragma unroll
            for (int q = 0; q < 4; q++) acc[i][j][q] = 0.f;

    const int NIT = Hh / BKg;   // 32
    stage_load(sbase, Ah, Bw, bm, bn, 0, tid);
    CP_COMMIT();
    stage_load(sbase + STAGE_B, Ah, Bw, bm, bn, BKg, tid);
    CP_COMMIT();
    CP_WAIT1();
    __syncthreads();

    for (int kt = 0; kt < NIT; kt++) {
        const uint32_t sb = sbase + (uint32_t)(kt % 3) * STAGE_B;
        if (kt + 2 < NIT) {
            stage_load(sbase + (uint32_t)((kt + 2) % 3) * STAGE_B,
                       Ah, Bw, bm, bn, (kt + 2) * BKg, tid);
            CP_COMMIT();
        }

        gemm_stage_compute(sb, acc, wm, wn, lane);

        if (kt + 1 < NIT) {
            if (kt + 2 < NIT) { CP_WAIT1(); } else { CP_WAIT0(); }
        }
        __syncthreads();
    }

    const int fr = lane >> 2;
    const int fc = (lane & 3) * 2;
#pragma unroll
    for (int mi = 0; mi < 2; mi++) {
#pragma unroll
        for (int ni = 0; ni < 4; ni++) {
            const int n0 = bn + wn + ni * 8 + fc;
            const float b0 = bias[n0], b1 = bias[n0 + 1];
#pragma unroll
            for (int half = 0; half < 2; half++) {
                const int m = bm + wm + mi * 16 + fr + half * 8;
                float2 w;
                w.x = acc[mi][ni][half * 2 + 0] + b0;
                w.y = acc[mi][ni][half * 2 + 1] + b1;
                *(float2*)&Cf[(size_t)m * Hh + n0] = w;
            }
        }
    }
}

// ---------------------------------------------------------------------------
// HMMA fp16 flash attention: single-fp16 Q/K/V, AKT=128, single sync/kt.
// CTA: 128 q rows, 8 warps x 16 rows. KV double-buffered cp.async. (R11 proven)
// ---------------------------------------------------------------------------
#define AQT 128
#define AKT 128
#define PADV 136
#define Q_TILE_B   (AQT * PADV * 2)        // 34816 bytes
#define KV_TILE_B  (AKT * PADV * 2)        // 34816 bytes
#define KV_STAGE_B (2 * KV_TILE_B)         // K, V = 69632 bytes
#define ATT2_SMEM  (Q_TILE_B + 2 * KV_STAGE_B)   // 174080 bytes

__device__ __forceinline__ void stage_kv2(uint32_t dst, size_t base, int kn0,
    const __half* __restrict__ Ks, const __half* __restrict__ Vs, int tid)
{
#pragma unroll
    for (int i = 0; i < 8; i++) {
        const int idx = i * 256 + tid;
        const int row = idx >> 4, ch = idx & 15;
        const uint32_t so = (uint32_t)(row * PADV + ch * 8) * 2;
        const size_t go = base + (size_t)(kn0 + row) * HDd + ch * 8;
        cp16(dst +             so, Ks + go);
        cp16(dst + KV_TILE_B + so, Vs + go);
    }
}

__global__ __launch_bounds__(256, 1)
void attn_mma(const __half* __restrict__ Qs, const __half* __restrict__ Ks,
              const __half* __restrict__ Vs, __half* __restrict__ AOh)
{
    extern __shared__ __half asmem[];
    const uint32_t sb = smem_to_u32(asmem);
    const uint32_t QH = sb, KV = sb + Q_TILE_B;
    const int tid = threadIdx.x, wid = tid >> 5, lane = tid & 31;
    const int qi = (int)gridDim.x - 1 - (int)blockIdx.x;   // big tiles first
    const int hh = blockIdx.y, bb = blockIdx.z;
    const size_t base = ((size_t)(bb * NHh + hh)) * Ss * HDd;
    const int q0 = qi * AQT;
    const float Cs = 0.12751745210319466f;   // 128^-0.5 * log2(e)

    const int qrow = wid * 16 + (lane & 15);
    const int qc8 = (lane >> 4) << 3;

    // ---- prologue: Q to resident smem; KV tile 0 in flight ----
#pragma unroll
    for (int i = 0; i < 8; i++) {
        const int idx = i * 256 + tid;
        const int row = idx >> 4, ch = idx & 15;
        cp16(QH + (uint32_t)(row * PADV + ch * 8) * 2,
             Qs + base + (size_t)(q0 + row) * HDd + ch * 8);
    }
    CP_COMMIT();
    stage_kv2(KV, base, 0, Ks, Vs, tid);
    CP_COMMIT();
    CP_WAIT1();          // Q ready
    __syncthreads();

    uint32_t qfh[8][4];
#pragma unroll
    for (int kk = 0; kk < 8; kk++)
        ldm_x4(qfh[kk][0], qfh[kk][1], qfh[kk][2], qfh[kk][3],
               QH + (uint32_t)(qrow * PADV + kk * 16 + qc8) * 2);

    float O[16][4];
#pragma unroll
    for (int i = 0; i < 16; i++)
#pragma unroll
        for (int j = 0; j < 4; j++) O[i][j] = 0.f;
    float m0 = -1e30f, m1 = -1e30f, l0 = 0.f, l1 = 0.f;

    const int nkt = qi + 1;
    for (int kt = 0; kt < nkt; kt++) {
        CP_WAIT0();          // KV(kt) resident
        __syncthreads();     // all warps done with KV(kt-1); visibility of KV(kt)
        if (kt + 1 < nkt) {
            stage_kv2(KV + (uint32_t)(((kt + 1) & 1) * KV_STAGE_B), base,
                      (kt + 1) * AKT, Ks, Vs, tid);
            CP_COMMIT();
        }
        const uint32_t cur = KV + (uint32_t)((kt & 1) * KV_STAGE_B);
        const uint32_t KsS = cur, VsS = cur + KV_TILE_B;

        // ---- scores: 16 n-frags over 128 keys, single-MMA ----
        float c[16][4];
#pragma unroll
        for (int i = 0; i < 16; i++)
#pragma unroll
            for (int j = 0; j < 4; j++) c[i][j] = 0.f;

#pragma unroll
        for (int kk = 0; kk < 8; kk++) {
            const uint32_t kc = (uint32_t)(kk * 16 + ((lane >> 3) & 1) * 8) * 2;
#pragma unroll
            for (int nfp = 0; nfp < 8; nfp++) {
                const uint32_t nrow =
                    (uint32_t)(nfp * 16 + ((lane >> 4) << 3) + (lane & 7));
                uint32_t h0, h1, h2, h3;
                ldm_x4(h0, h1, h2, h3, KsS + nrow * (PADV * 2) + kc);
                uint32_t bA[2] = {h0, h1}, bB[2] = {h2, h3};
                mma_f16(c[2 * nfp],     qfh[kk], bA);
                mma_f16(c[2 * nfp + 1], qfh[kk], bB);
            }
        }

        // ---- causal mask (only the diagonal tile) ----
        if (kt == nkt - 1) {
            const int row0 = q0 + wid * 16 + (lane >> 2);
            const int col0 = kt * AKT + (lane & 3) * 2;
#pragma unroll
            for (int nf = 0; nf < 16; nf++) {
                const int cb = col0 + nf * 8;
                if (cb     > row0)     c[nf][0] = -1e30f;
                if (cb + 1 > row0)     c[nf][1] = -1e30f;
                if (cb     > row0 + 8) c[nf][2] = -1e30f;
                if (cb + 1 > row0 + 8) c[nf][3] = -1e30f;
            }
        }

        // ---- online softmax ----
        float rm0 = -1e30f, rm1 = -1e30f;
#pragma unroll
        for (int nf = 0; nf < 16; nf++) {
            rm0 = fmaxf(rm0, fmaxf(c[nf][0], c[nf][1]));
            rm1 = fmaxf(rm1, fmaxf(c[nf][2], c[nf][3]));
        }
        rm0 = fmaxf(rm0, __shfl_xor_sync(0xffffffffu, rm0, 1));
        rm0 = fmaxf(rm0, __shfl_xor_sync(0xffffffffu, rm0, 2));
        rm1 = fmaxf(rm1, __shfl_xor_sync(0xffffffffu, rm1, 1));
        rm1 = fmaxf(rm1, __shfl_xor_sync(0xffffffffu, rm1, 2));
        const float mn0 = fmaxf(m0, rm0), mn1 = fmaxf(m1, rm1);
        const float a0 = exp2p((m0 - mn0) * Cs);
        const float a1 = exp2p((m1 - mn1) * Cs);
        m0 = mn0; m1 = mn1;

        float rs0 = 0.f, rs1 = 0.f;
#pragma unroll
        for (int nf = 0; nf < 16; nf++) {
            c[nf][0] = exp2p((c[nf][0] - mn0) * Cs);
            c[nf][1] = exp2p((c[nf][1] - mn0) * Cs);
            c[nf][2] = exp2p((c[nf][2] - mn1) * Cs);
            c[nf][3] = exp2p((c[nf][3] - mn1) * Cs);
            rs0 += c[nf][0] + c[nf][1];
            rs1 += c[nf][2] + c[nf][3];
        }
        rs0 += __shfl_xor_sync(0xffffffffu, rs0, 1);
        rs0 += __shfl_xor_sync(0xffffffffu, rs0, 2);
        rs1 += __shfl_xor_sync(0xffffffffu, rs1, 1);
        rs1 += __shfl_xor_sync(0xffffffffu, rs1, 2);
        l0 = l0 * a0 + rs0;
        l1 = l1 * a1 + rs1;

#pragma unroll
        for (int i = 0; i < 16; i++) {
            O[i][0] *= a0; O[i][1] *= a0; O[i][2] *= a1; O[i][3] *= a1;
        }

        // ---- O += P @ V (P packed on the fly per 16-key group) ----
#pragma unroll
        for (int k2 = 0; k2 < 8; k2++) {
            uint32_t pah[4];
#pragma unroll
            for (int q = 0; q < 4; q++) {
                const int nf = 2 * k2 + (q >> 1);
                const int e  = (q & 1) * 2;
                pah[q] = packh(c[nf][e], c[nf][e + 1]);
            }
            const uint32_t vr =
                (uint32_t)(k2 * 16 + (lane & 7) + ((lane >> 3) & 1) * 8);
#pragma unroll
            for (int nfp = 0; nfp < 8; nfp++) {
                const uint32_t vc = (uint32_t)(nfp * 16 + ((lane >> 4) << 3));
                uint32_t h0, h1, h2, h3;
                ldm_x4t(h0, h1, h2, h3, VsS + (vr * PADV + vc) * 2);
                uint32_t bA[2] = {h0, h1}, bB[2] = {h2, h3};
                mma_f16(O[2 * nfp],     pah, bA);
                mma_f16(O[2 * nfp + 1], pah, bB);
            }
        }
    }

    // ---- epilogue: normalize, write AO single fp16 [B,S,H] ----
    const float inv0 = 1.f / l0, inv1 = 1.f / l1;
    const int srow0 = q0 + wid * 16 + (lane >> 2);
#pragma unroll
    for (int nf = 0; nf < 16; nf++) {
        const int col = hh * HDd + nf * 8 + (lane & 3) * 2;
        const size_t o0 = ((size_t)(bb * Ss) + srow0) * Hh + col;
        const size_t o1 = o0 + (size_t)8 * Hh;
        *(uint32_t*)&AOh[o0] = packh(O[nf][0] * inv0, O[nf][1] * inv0);
        *(uint32_t*)&AOh[o1] = packh(O[nf][2] * inv1, O[nf][3] * inv1);
    }
}

// ---------------------------------------------------------------------------
extern "C" void kernel_launch(void* const* d_in, const int* in_sizes, int n_in,
                              void* d_out, int out_size)
{
    (void)in_sizes; (void)n_in; (void)out_size;
    const float* x  = (const float*)d_in[0];
    const float* wq = (const float*)d_in[2];
    const float* bq = (const float*)d_in[3];
    const float* wk = (const float*)d_in[4];
    const float* bk = (const float*)d_in[5];
    const float* wv = (const float*)d_in[6];
    const float* bv = (const float*)d_in[7];
    const float* wo = (const float*)d_in[8];
    const float* bo = (const float*)d_in[9];
    float* out = (float*)d_out;

    __half *xs, *qs, *ks, *vs, *aoh, *wt;
    cudaGetSymbolAddress((void**)&xs,  g_Xs);
    cudaGetSymbolAddress((void**)&qs,  g_Qs);
    cudaGetSymbolAddress((void**)&ks,  g_Ks);
    cudaGetSymbolAddress((void**)&vs,  g_Vs);
    cudaGetSymbolAddress((void**)&aoh, g_AOh);
    cudaGetSymbolAddress((void**)&wt,  g_Wt);
    const size_t WSZ = (size_t)Hh * Hh;

    static bool attr_set = false;
    if (!attr_set) {
        cudaFuncSetAttribute(qkv_mma,
                             cudaFuncAttributeMaxDynamicSharedMemorySize, GEMM_SMEM);
        cudaFuncSetAttribute(proj_mma,
                             cudaFuncAttributeMaxDynamicSharedMemorySize, GEMM_SMEM);
        cudaFuncSetAttribute(attn_mma,
                             cudaFuncAttributeMaxDynamicSharedMemorySize, ATT2_SMEM);
        attr_set = true;
    }

    const int N2 = Mm * Hh / 2;
    convert_half<<<(N2 + 255) / 256, 256>>>(
        (const float2*)x, (__half2*)xs, N2);

    transpose_convert4<<<dim3(Hh / 32, Hh / 32, 4), dim3(32, 8)>>>(
        wq, wk, wv, wo, wt);

    // Q, K, V in one uniform launch (z selects weight/bias/output)
    qkv_mma<<<dim3(Hh / 128, Mm / 128, 3), 512, GEMM_SMEM>>>(
        xs, wt, bq, bk, bv, qs, ks, vs);

    attn_mma<<<dim3(Ss / AQT, NHh, Bb), 256, ATT2_SMEM>>>(qs, ks, vs, aoh);

    proj_mma<<<dim3(Hh / 128, Mm / 128), 512, GEMM_SMEM>>>(
        aoh, wt + 3 * WSZ, bo, out);
}